// round 1
// baseline (speedup 1.0000x reference)
#include <cuda_runtime.h>
#include <math.h>
#include <stdint.h>

#define NPTS 32768
#define DMODEL 256
#define NH 8
#define DHEAD 32
#define QKDIM 128
#define NLAYERS 5

// ---------------- static device scratch (no allocs allowed) ----------------
__device__ float g_fx[NPTS * DMODEL];
__device__ float g_t1[NPTS * DMODEL];
__device__ float g_t2[NPTS * DMODEL];
__device__ float g_t3[NPTS * DMODEL];
__device__ float g_hidden[NPTS * 512];
__device__ float g_kv[NH * QKDIM * DHEAD];
__device__ float g_S[NH * QKDIM];

__device__ __forceinline__ float gelu_f(float x) {
    return 0.5f * x * (1.0f + erff(x * 0.70710678118654752f));
}

// block-wide sum for 256 threads; result broadcast to all threads
__device__ __forceinline__ float block_sum256(float v, volatile float* sh) {
    int lane = threadIdx.x & 31;
#pragma unroll
    for (int o = 16; o > 0; o >>= 1) v += __shfl_down_sync(0xffffffffu, v, o);
    if (lane == 0) sh[threadIdx.x >> 5] = v;
    __syncthreads();
    if (threadIdx.x < 32) {
        float r = (lane < 8) ? sh[lane] : 0.f;
#pragma unroll
        for (int o = 4; o > 0; o >>= 1) r += __shfl_down_sync(0xffffffffu, r, o);
        if (lane == 0) sh[0] = r;
    }
    __syncthreads();
    float out = sh[0];
    __syncthreads();
    return out;
}

// ---------------- preprocess: hidden = gelu(x @ pre_w1 + b1) ----------------
__global__ void pre1_kernel(const float* __restrict__ x, const float* __restrict__ w1,
                            const float* __restrict__ b1, float* __restrict__ hidden) {
    int idx = blockIdx.x * 256 + threadIdx.x;  // NPTS*512 total
    int n = idx >> 9, j = idx & 511;
    float x0 = x[n * 3 + 0], x1 = x[n * 3 + 1], x2 = x[n * 3 + 2];
    float a = x0 * w1[j] + x1 * w1[512 + j] + x2 * w1[1024 + j] + b1[j];
    hidden[idx] = gelu_f(a);
}

// ---------------- tiled SGEMM: Y[N,256] = act(A[N,K] @ W[K,256] + bias + colbias) + residual
#define BM 64
#define BN 64
#define BK 16
__global__ void gemm_kernel(const float* __restrict__ A, int K,
                            const float* __restrict__ W,
                            const float* __restrict__ bias,
                            const float* __restrict__ colbias,
                            const float* __restrict__ residual,
                            float* __restrict__ Y, int act) {
    __shared__ float As[BK][BM];
    __shared__ float Bs[BK][BN];
    int m0 = blockIdx.x * BM;
    int n0 = blockIdx.y * BN;
    int tid = threadIdx.x;
    int tm = tid >> 4, tn = tid & 15;
    int arow = tid >> 2, acg = (tid & 3) * 4;
    int brow = tid >> 4, bcg = (tid & 15) * 4;
    float acc[4][4] = {};

    for (int k0 = 0; k0 < K; k0 += BK) {
        float4 av = *(const float4*)(A + (size_t)(m0 + arow) * K + k0 + acg);
        float4 bv = *(const float4*)(W + (size_t)(k0 + brow) * DMODEL + n0 + bcg);
        As[acg + 0][arow] = av.x;
        As[acg + 1][arow] = av.y;
        As[acg + 2][arow] = av.z;
        As[acg + 3][arow] = av.w;
        *(float4*)(&Bs[brow][bcg]) = bv;
        __syncthreads();
#pragma unroll
        for (int k = 0; k < BK; k++) {
            float4 a = *(const float4*)(&As[k][tm * 4]);
            float4 b = *(const float4*)(&Bs[k][tn * 4]);
            acc[0][0] += a.x * b.x; acc[0][1] += a.x * b.y; acc[0][2] += a.x * b.z; acc[0][3] += a.x * b.w;
            acc[1][0] += a.y * b.x; acc[1][1] += a.y * b.y; acc[1][2] += a.y * b.z; acc[1][3] += a.y * b.w;
            acc[2][0] += a.z * b.x; acc[2][1] += a.z * b.y; acc[2][2] += a.z * b.z; acc[2][3] += a.z * b.w;
            acc[3][0] += a.w * b.x; acc[3][1] += a.w * b.y; acc[3][2] += a.w * b.z; acc[3][3] += a.w * b.w;
        }
        __syncthreads();
    }
#pragma unroll
    for (int i = 0; i < 4; i++) {
        int row = m0 + tm * 4 + i;
#pragma unroll
        for (int j = 0; j < 4; j++) {
            int col = n0 + tn * 4 + j;
            float v = acc[i][j];
            if (bias) v += bias[col];
            if (colbias) v += colbias[col];
            if (act) v = gelu_f(v);
            if (residual) v += residual[(size_t)row * DMODEL + col];
            Y[(size_t)row * DMODEL + col] = v;
        }
    }
}

// ---------------- LayerNorm (row-wise, D=256) ----------------
__global__ void ln_kernel(const float* __restrict__ X, const float* __restrict__ g,
                          const float* __restrict__ b, float* __restrict__ Y) {
    __shared__ float sh[8];
    int n = blockIdx.x, t = threadIdx.x;
    float v = X[(size_t)n * DMODEL + t];
    float mean = block_sum256(v, sh) * (1.0f / DMODEL);
    float d = v - mean;
    float var = block_sum256(d * d, sh) * (1.0f / DMODEL);
    float rstd = rsqrtf(var + 1e-5f);
    Y[(size_t)n * DMODEL + t] = d * rstd * g[t] + b[t];
}

// ---------------- zero kv accumulators ----------------
__global__ void zero_kv_kernel() {
    int idx = blockIdx.x * 256 + threadIdx.x;
    if (idx < NH * QKDIM * DHEAD) g_kv[idx] = 0.f;
    if (idx < NH * QKDIM) g_S[idx] = 0.f;
}

// ---------------- KV accumulation: kv[h,e,c] += exp(kl/tk)*v ; S[h,e] += exp(kl/tk)
// grid: (32 chunks of 1024 rows, 8 heads), 256 threads
__global__ void kv_kernel(const float* __restrict__ xm, const float* __restrict__ wk,
                          const float* __restrict__ wv, const float* __restrict__ temp_k) {
    __shared__ float wk_s[32][128];
    __shared__ float wv_s[32][32];
    __shared__ float xm_s[32][32];
    __shared__ float v_s[32][32];
    __shared__ float kexp_s[32][128];
    int h = blockIdx.y;
    int tid = threadIdx.x;
    int row0 = blockIdx.x * 1024;

    for (int idx = tid; idx < 32 * 128; idx += 256) wk_s[idx >> 7][idx & 127] = wk[idx];
    for (int idx = tid; idx < 32 * 32; idx += 256) wv_s[idx >> 5][idx & 31] = wv[idx];
    float tk = fminf(fmaxf(temp_k[h], 0.1f), 2.0f);
    float itk = 1.0f / tk;

    int e_me = tid & 127, r0 = tid >> 7;  // kexp mapping
    int cc = tid & 31, eg = tid >> 5;     // kv-acc mapping: e = eg + 8k
    float acc[16] = {};
    float sloc = 0.f;

    for (int s = 0; s < 1024; s += 32) {
        __syncthreads();
        {   // stage xm tile [32 rows][32 dims]
            int rr = tid >> 5, d = tid & 31;
            for (int r = rr; r < 32; r += 8)
                xm_s[r][d] = xm[(size_t)(row0 + s + r) * DMODEL + h * DHEAD + d];
        }
        __syncthreads();
        {   // v = xm @ wv
            int rr = tid >> 5, c = tid & 31;
            for (int r = rr; r < 32; r += 8) {
                float a = 0.f;
#pragma unroll
                for (int d = 0; d < 32; d++) a += xm_s[r][d] * wv_s[d][c];
                v_s[r][c] = a;
            }
        }
        // kexp = exp((xm @ wk) / tk)
        for (int r = r0; r < 32; r += 2) {
            float a = 0.f;
#pragma unroll
            for (int d = 0; d < 32; d++) a += xm_s[r][d] * wk_s[d][e_me];
            float ke = expf(a * itk);
            kexp_s[r][e_me] = ke;
            sloc += ke;
        }
        __syncthreads();
        // accumulate kv partials
        for (int r = 0; r < 32; r++) {
            float vv = v_s[r][cc];
#pragma unroll
            for (int k2 = 0; k2 < 16; k2++) acc[k2] += kexp_s[r][eg + (k2 << 3)] * vv;
        }
    }
#pragma unroll
    for (int k2 = 0; k2 < 16; k2++)
        atomicAdd(&g_kv[(h * QKDIM + eg + (k2 << 3)) * DHEAD + cc], acc[k2]);
    atomicAdd(&g_S[h * QKDIM + e_me], sloc);
}

// ---------------- QKV: q = softmax_row((xm@wq)/tq); out = q @ (kv/S)
// grid: (1024 tiles of 32 rows, 8 heads), 256 threads
__global__ void qkv_kernel(const float* __restrict__ xm, const float* __restrict__ wq,
                           const float* __restrict__ temp_q, float* __restrict__ out) {
    __shared__ float wq_s[32][128];
    __shared__ float kv_s[128][32];
    __shared__ float qs[32][128];
    int h = blockIdx.y;
    int row0 = blockIdx.x * 32;
    int tid = threadIdx.x;

    for (int idx = tid; idx < 32 * 128; idx += 256) wq_s[idx >> 7][idx & 127] = wq[idx];
    for (int idx = tid; idx < 128 * 32; idx += 256) {
        int e = idx >> 5, c = idx & 31;
        kv_s[e][c] = g_kv[(h * QKDIM + e) * DHEAD + c] / g_S[h * QKDIM + e];
    }
    float tq = fminf(fmaxf(temp_q[h], 0.1f), 2.0f);
    float itq = 1.0f / tq;
    __syncthreads();

    // q logits
    {
        int e_me = tid & 127, r0 = tid >> 7;
        for (int r = r0; r < 32; r += 2) {
            const float* xr = xm + (size_t)(row0 + r) * DMODEL + h * DHEAD;
            float a = 0.f;
#pragma unroll
            for (int d = 0; d < 32; d++) a += xr[d] * wq_s[d][e_me];
            qs[r][e_me] = a * itq;
        }
    }
    __syncthreads();
    // row softmax over 128: 8 threads/row, 16 elems each
    {
        int r = tid >> 3, sub = tid & 7;
        float mx = -1e30f;
#pragma unroll
        for (int k = 0; k < 16; k++) mx = fmaxf(mx, qs[r][sub + (k << 3)]);
#pragma unroll
        for (int o = 4; o > 0; o >>= 1) mx = fmaxf(mx, __shfl_xor_sync(0xffffffffu, mx, o));
        float ev[16];
        float sm = 0.f;
#pragma unroll
        for (int k = 0; k < 16; k++) { ev[k] = expf(qs[r][sub + (k << 3)] - mx); sm += ev[k]; }
#pragma unroll
        for (int o = 4; o > 0; o >>= 1) sm += __shfl_xor_sync(0xffffffffu, sm, o);
        float inv = 1.0f / sm;
#pragma unroll
        for (int k = 0; k < 16; k++) qs[r][sub + (k << 3)] = ev[k] * inv;
    }
    __syncthreads();
    // qkv = q @ kv_s  -> out[n, h*32+c]
    {
        int c = tid & 31, rb = (tid >> 5) * 4;
        float a0 = 0.f, a1 = 0.f, a2 = 0.f, a3 = 0.f;
        for (int e = 0; e < 128; e++) {
            float kvv = kv_s[e][c];
            a0 += qs[rb + 0][e] * kvv;
            a1 += qs[rb + 1][e] * kvv;
            a2 += qs[rb + 2][e] * kvv;
            a3 += qs[rb + 3][e] * kvv;
        }
        out[(size_t)(row0 + rb + 0) * DMODEL + h * DHEAD + c] = a0;
        out[(size_t)(row0 + rb + 1) * DMODEL + h * DHEAD + c] = a1;
        out[(size_t)(row0 + rb + 2) * DMODEL + h * DHEAD + c] = a2;
        out[(size_t)(row0 + rb + 3) * DMODEL + h * DHEAD + c] = a3;
    }
}

// ---------------- head: out[n] = LN(fx) @ head_w + head_b ----------------
__global__ void head_kernel(const float* __restrict__ fx, const float* __restrict__ g,
                            const float* __restrict__ b, const float* __restrict__ hw,
                            const float* __restrict__ hb, float* __restrict__ out) {
    __shared__ float sh[8];
    int n = blockIdx.x, t = threadIdx.x;
    float v = fx[(size_t)n * DMODEL + t];
    float mean = block_sum256(v, sh) * (1.0f / DMODEL);
    float d = v - mean;
    float var = block_sum256(d * d, sh) * (1.0f / DMODEL);
    float rstd = rsqrtf(var + 1e-5f);
    float hn = d * rstd * g[t] + b[t];
    float dot = block_sum256(hn * hw[t], sh);
    if (t == 0) out[n] = dot + hb[0];
}

// ---------------- launch ----------------
extern "C" void kernel_launch(void* const* d_in, const int* in_sizes, int n_in,
                              void* d_out, int out_size) {
    const float* x          = (const float*)d_in[0];
    const float* pre_w1     = (const float*)d_in[1];
    const float* pre_b1     = (const float*)d_in[2];
    const float* pre_w2     = (const float*)d_in[3];
    const float* pre_b2     = (const float*)d_in[4];
    const float* placeholder= (const float*)d_in[5];
    const float* ln1_g      = (const float*)d_in[6];
    const float* ln1_b      = (const float*)d_in[7];
    const float* inp_w      = (const float*)d_in[8];
    const float* inp_b      = (const float*)d_in[9];
    const float* temp_q     = (const float*)d_in[10];
    const float* temp_k     = (const float*)d_in[11];
    const float* wq         = (const float*)d_in[12];
    const float* wk         = (const float*)d_in[13];
    const float* wv         = (const float*)d_in[14];
    const float* out_w1     = (const float*)d_in[15];
    const float* out_b1     = (const float*)d_in[16];
    const float* out_w2     = (const float*)d_in[17];
    const float* out_b2     = (const float*)d_in[18];
    const float* ln2_g      = (const float*)d_in[19];
    const float* ln2_b      = (const float*)d_in[20];
    const float* mlp_w1     = (const float*)d_in[21];
    const float* mlp_b1     = (const float*)d_in[22];
    const float* mlp_w2     = (const float*)d_in[23];
    const float* mlp_b2     = (const float*)d_in[24];
    const float* ln3_g      = (const float*)d_in[25];
    const float* ln3_b      = (const float*)d_in[26];
    const float* head_w     = (const float*)d_in[27];
    const float* head_b     = (const float*)d_in[28];

    float *fx, *t1, *t2, *t3, *hidden;
    cudaGetSymbolAddress((void**)&fx, g_fx);
    cudaGetSymbolAddress((void**)&t1, g_t1);
    cudaGetSymbolAddress((void**)&t2, g_t2);
    cudaGetSymbolAddress((void**)&t3, g_t3);
    cudaGetSymbolAddress((void**)&hidden, g_hidden);

    dim3 ggrid(NPTS / BM, DMODEL / BN);

    // preprocess
    pre1_kernel<<<NPTS * 512 / 256, 256>>>(x, pre_w1, pre_b1, hidden);
    gemm_kernel<<<ggrid, 256>>>(hidden, 512, pre_w2, pre_b2, placeholder, nullptr, fx, 0);

    for (int i = 0; i < NLAYERS; i++) {
        const float* iw  = inp_w + (size_t)i * 65536;
        const float* ow1 = out_w1 + (size_t)i * 65536;
        const float* ow2 = out_w2 + (size_t)i * 65536;
        const float* mw1 = mlp_w1 + (size_t)i * 65536;
        const float* mw2 = mlp_w2 + (size_t)i * 65536;

        ln_kernel<<<NPTS, 256>>>(fx, ln1_g + i * 256, ln1_b + i * 256, t1);
        gemm_kernel<<<ggrid, 256>>>(t1, 256, iw, inp_b + i * 256, nullptr, nullptr, t2, 0);
        zero_kv_kernel<<<(NH * QKDIM * DHEAD + 255) / 256, 256>>>();
        kv_kernel<<<dim3(32, NH), 256>>>(t2, wk + (size_t)i * 4096, wv + (size_t)i * 1024,
                                         temp_k + i * NH);
        qkv_kernel<<<dim3(NPTS / 32, NH), 256>>>(t2, wq + (size_t)i * 4096, temp_q + i * NH, t3);
        gemm_kernel<<<ggrid, 256>>>(t3, 256, ow1, out_b1 + i * 256, nullptr, nullptr, t1, 1);
        gemm_kernel<<<ggrid, 256>>>(t1, 256, ow2, out_b2 + i * 256, nullptr, fx, fx, 0);
        ln_kernel<<<NPTS, 256>>>(fx, ln2_g + i * 256, ln2_b + i * 256, t1);
        gemm_kernel<<<ggrid, 256>>>(t1, 256, mw1, mlp_b1 + i * 256, nullptr, nullptr, t2, 1);
        gemm_kernel<<<ggrid, 256>>>(t2, 256, mw2, mlp_b2 + i * 256, nullptr, fx, fx, 0);
    }
    head_kernel<<<NPTS, 256>>>(fx, ln3_g, ln3_b, head_w, head_b, (float*)d_out);
}

// round 2
// speedup vs baseline: 1.5086x; 1.5086x over previous
#include <cuda_runtime.h>
#include <math.h>
#include <stdint.h>

#define NPTS 32768
#define DMODEL 256
#define NH 8
#define DHEAD 32
#define QKDIM 128
#define NLAYERS 5

// ---------------- static device scratch (no allocs allowed) ----------------
__device__ float g_fx[NPTS * DMODEL];
__device__ float g_t1[NPTS * DMODEL];
__device__ float g_t2[NPTS * DMODEL];
__device__ float g_t3[NPTS * DMODEL];
__device__ float g_hidden[NPTS * 512];
__device__ float g_kv[NH * QKDIM * DHEAD];
__device__ float g_S[NH * QKDIM];

__device__ __forceinline__ float gelu_f(float x) {
    return 0.5f * x * (1.0f + erff(x * 0.70710678118654752f));
}

__device__ __forceinline__ float to_tf32(float x) {
    uint32_t u;
    asm("cvt.rna.tf32.f32 %0, %1;" : "=r"(u) : "f"(x));
    return __uint_as_float(u);
}

__device__ __forceinline__ void mma_tf32(float* c, const uint32_t* a, const uint32_t* b) {
    asm volatile(
        "mma.sync.aligned.m16n8k8.row.col.f32.tf32.tf32.f32 "
        "{%0,%1,%2,%3}, {%4,%5,%6,%7}, {%8,%9}, {%0,%1,%2,%3};\n"
        : "+f"(c[0]), "+f"(c[1]), "+f"(c[2]), "+f"(c[3])
        : "r"(a[0]), "r"(a[1]), "r"(a[2]), "r"(a[3]), "r"(b[0]), "r"(b[1]));
}

// block-wide sum for 256 threads; result broadcast to all threads
__device__ __forceinline__ float block_sum256(float v, volatile float* sh) {
    int lane = threadIdx.x & 31;
#pragma unroll
    for (int o = 16; o > 0; o >>= 1) v += __shfl_down_sync(0xffffffffu, v, o);
    if (lane == 0) sh[threadIdx.x >> 5] = v;
    __syncthreads();
    if (threadIdx.x < 32) {
        float r = (lane < 8) ? sh[lane] : 0.f;
#pragma unroll
        for (int o = 4; o > 0; o >>= 1) r += __shfl_down_sync(0xffffffffu, r, o);
        if (lane == 0) sh[0] = r;
    }
    __syncthreads();
    float out = sh[0];
    __syncthreads();
    return out;
}

// ---------------- preprocess: hidden = gelu(x @ pre_w1 + b1) ----------------
__global__ void pre1_kernel(const float* __restrict__ x, const float* __restrict__ w1,
                            const float* __restrict__ b1, float* __restrict__ hidden) {
    int idx = blockIdx.x * 256 + threadIdx.x;  // NPTS*512 total
    int n = idx >> 9, j = idx & 511;
    float x0 = x[n * 3 + 0], x1 = x[n * 3 + 1], x2 = x[n * 3 + 2];
    float a = x0 * w1[j] + x1 * w1[512 + j] + x2 * w1[1024 + j] + b1[j];
    hidden[idx] = gelu_f(a);
}

// ---------------- tf32 tensor-core GEMM ----------------
// Y[N,256] = act(A[N,K] @ W[K,256] + bias + colbias) + residual
// Block tile 128x128, BK=32. 8 warps, each 64x32 (4x4 of m16n8k8).
#define TBM 128
#define TBN 128
#define TBK 32
__global__ __launch_bounds__(256, 2)
void gemm_kernel(const float* __restrict__ A, int K,
                 const float* __restrict__ W,
                 const float* __restrict__ bias,
                 const float* __restrict__ colbias,
                 const float* __restrict__ residual,
                 float* __restrict__ Y, int act) {
    __shared__ float As[TBM][TBK + 4];   // [m][k], pad 4 -> frag bank = 4r+c (conflict-free)
    __shared__ float Bs[TBK][TBN + 8];   // [k][n], pad 8 -> frag bank = 8k+n (conflict-free)

    int m0 = blockIdx.x * TBM;
    int n0 = blockIdx.y * TBN;
    int tid = threadIdx.x;
    int wid = tid >> 5, lane = tid & 31;
    int wm = (wid >> 2) * 64;   // warp m offset in block (0 or 64)
    int wn = (wid & 3) * 32;    // warp n offset in block (0..96)
    int lr = lane >> 2;         // 0..7
    int lc = lane & 3;          // 0..3

    float acc[4][4][4];
#pragma unroll
    for (int i = 0; i < 4; i++)
#pragma unroll
        for (int j = 0; j < 4; j++)
#pragma unroll
            for (int k = 0; k < 4; k++) acc[i][j][k] = 0.f;

    // staging maps
    int a_r = tid >> 3;            // 0..31 (row group)
    int a_kc = (tid & 7) * 4;      // k offset
    int b_kr = tid >> 5;           // 0..7
    int b_nc = lane * 4;           // 0..124

    for (int k0 = 0; k0 < K; k0 += TBK) {
        // stage A: 128 x 32
#pragma unroll
        for (int rr = 0; rr < 4; rr++) {
            int row = a_r + rr * 32;
            float4 v = *(const float4*)(A + (size_t)(m0 + row) * K + k0 + a_kc);
            float4 c4;
            c4.x = to_tf32(v.x); c4.y = to_tf32(v.y);
            c4.z = to_tf32(v.z); c4.w = to_tf32(v.w);
            *(float4*)(&As[row][a_kc]) = c4;
        }
        // stage B: 32 x 128
#pragma unroll
        for (int kk = 0; kk < 4; kk++) {
            int krow = b_kr + kk * 8;
            float4 v = *(const float4*)(W + (size_t)(k0 + krow) * DMODEL + n0 + b_nc);
            float4 c4;
            c4.x = to_tf32(v.x); c4.y = to_tf32(v.y);
            c4.z = to_tf32(v.z); c4.w = to_tf32(v.w);
            *(float4*)(&Bs[krow][b_nc]) = c4;
        }
        __syncthreads();

#pragma unroll
        for (int ks = 0; ks < TBK; ks += 8) {
            uint32_t af[4][4], bf[4][2];
#pragma unroll
            for (int mt = 0; mt < 4; mt++) {
                int r = wm + mt * 16 + lr;
                int c = ks + lc;
                af[mt][0] = __float_as_uint(As[r][c]);
                af[mt][1] = __float_as_uint(As[r + 8][c]);
                af[mt][2] = __float_as_uint(As[r][c + 4]);
                af[mt][3] = __float_as_uint(As[r + 8][c + 4]);
            }
#pragma unroll
            for (int nt = 0; nt < 4; nt++) {
                int n = wn + nt * 8 + lr;
                int c = ks + lc;
                bf[nt][0] = __float_as_uint(Bs[c][n]);
                bf[nt][1] = __float_as_uint(Bs[c + 4][n]);
            }
#pragma unroll
            for (int mt = 0; mt < 4; mt++)
#pragma unroll
                for (int nt = 0; nt < 4; nt++)
                    mma_tf32(acc[mt][nt], af[mt], bf[nt]);
        }
        __syncthreads();
    }

    // epilogue: c0,c1 at (row, col..col+1), c2,c3 at (row+8, col..col+1)
#pragma unroll
    for (int mt = 0; mt < 4; mt++) {
        int row = m0 + wm + mt * 16 + lr;
#pragma unroll
        for (int nt = 0; nt < 4; nt++) {
            int col = n0 + wn + nt * 8 + lc * 2;
#pragma unroll
            for (int half = 0; half < 2; half++) {
                int r = row + half * 8;
                float v0 = acc[mt][nt][half * 2 + 0];
                float v1 = acc[mt][nt][half * 2 + 1];
                if (bias)    { v0 += bias[col];        v1 += bias[col + 1]; }
                if (colbias) { v0 += colbias[col];     v1 += colbias[col + 1]; }
                if (act)     { v0 = gelu_f(v0);        v1 = gelu_f(v1); }
                if (residual) {
                    v0 += residual[(size_t)r * DMODEL + col];
                    v1 += residual[(size_t)r * DMODEL + col + 1];
                }
                float2 o; o.x = v0; o.y = v1;
                *(float2*)(Y + (size_t)r * DMODEL + col) = o;
            }
        }
    }
}

// ---------------- LayerNorm (row-wise, D=256) ----------------
__global__ void ln_kernel(const float* __restrict__ X, const float* __restrict__ g,
                          const float* __restrict__ b, float* __restrict__ Y) {
    __shared__ float sh[8];
    int n = blockIdx.x, t = threadIdx.x;
    float v = X[(size_t)n * DMODEL + t];
    float mean = block_sum256(v, sh) * (1.0f / DMODEL);
    float d = v - mean;
    float var = block_sum256(d * d, sh) * (1.0f / DMODEL);
    float rstd = rsqrtf(var + 1e-5f);
    Y[(size_t)n * DMODEL + t] = d * rstd * g[t] + b[t];
}

// ---------------- zero kv accumulators ----------------
__global__ void zero_kv_kernel() {
    int idx = blockIdx.x * 256 + threadIdx.x;
    if (idx < NH * QKDIM * DHEAD) g_kv[idx] = 0.f;
    if (idx < NH * QKDIM) g_S[idx] = 0.f;
}

// ---------------- KV accumulation: kv[h,e,c] += exp(kl/tk)*v ; S[h,e] += exp(kl/tk)
// grid: (64 chunks of 512 rows, 8 heads), 256 threads
__global__ void kv_kernel(const float* __restrict__ xm, const float* __restrict__ wk,
                          const float* __restrict__ wv, const float* __restrict__ temp_k) {
    __shared__ float wk_s[32][128];
    __shared__ float wv_s[32][32];
    __shared__ float xm_s[32][32];
    __shared__ float v_s[32][32];
    __shared__ float kexp_s[32][128];
    int h = blockIdx.y;
    int tid = threadIdx.x;
    int row0 = blockIdx.x * 512;

    for (int idx = tid; idx < 32 * 128; idx += 256) wk_s[idx >> 7][idx & 127] = wk[idx];
    for (int idx = tid; idx < 32 * 32; idx += 256) wv_s[idx >> 5][idx & 31] = wv[idx];
    float tk = fminf(fmaxf(temp_k[h], 0.1f), 2.0f);
    float itk = 1.0f / tk;

    int e_me = tid & 127, r0 = tid >> 7;  // kexp mapping
    int cc = tid & 31, eg = tid >> 5;     // kv-acc mapping: e = eg + 8k
    float acc[16] = {};
    float sloc = 0.f;

    for (int s = 0; s < 512; s += 32) {
        __syncthreads();
        {   // stage xm tile [32 rows][32 dims]
            int rr = tid >> 5, d = tid & 31;
            for (int r = rr; r < 32; r += 8)
                xm_s[r][d] = xm[(size_t)(row0 + s + r) * DMODEL + h * DHEAD + d];
        }
        __syncthreads();
        {   // v = xm @ wv
            int rr = tid >> 5, c = tid & 31;
            for (int r = rr; r < 32; r += 8) {
                float a = 0.f;
#pragma unroll
                for (int d = 0; d < 32; d++) a += xm_s[r][d] * wv_s[d][c];
                v_s[r][c] = a;
            }
        }
        // kexp = exp((xm @ wk) / tk)
        for (int r = r0; r < 32; r += 2) {
            float a = 0.f;
#pragma unroll
            for (int d = 0; d < 32; d++) a += xm_s[r][d] * wk_s[d][e_me];
            float ke = expf(a * itk);
            kexp_s[r][e_me] = ke;
            sloc += ke;
        }
        __syncthreads();
        // accumulate kv partials
        for (int r = 0; r < 32; r++) {
            float vv = v_s[r][cc];
#pragma unroll
            for (int k2 = 0; k2 < 16; k2++) acc[k2] += kexp_s[r][eg + (k2 << 3)] * vv;
        }
    }
#pragma unroll
    for (int k2 = 0; k2 < 16; k2++)
        atomicAdd(&g_kv[(h * QKDIM + eg + (k2 << 3)) * DHEAD + cc], acc[k2]);
    atomicAdd(&g_S[h * QKDIM + e_me], sloc);
}

// ---------------- QKV: q = softmax_row((xm@wq)/tq); out = q @ (kv/S)
// grid: (1024 tiles of 32 rows, 8 heads), 256 threads
__global__ void qkv_kernel(const float* __restrict__ xm, const float* __restrict__ wq,
                           const float* __restrict__ temp_q, float* __restrict__ out) {
    __shared__ float wq_s[32][128];
    __shared__ float kv_s[128][32];
    __shared__ float qs[32][128];
    int h = blockIdx.y;
    int row0 = blockIdx.x * 32;
    int tid = threadIdx.x;

    for (int idx = tid; idx < 32 * 128; idx += 256) wq_s[idx >> 7][idx & 127] = wq[idx];
    for (int idx = tid; idx < 128 * 32; idx += 256) {
        int e = idx >> 5, c = idx & 31;
        kv_s[e][c] = g_kv[(h * QKDIM + e) * DHEAD + c] / g_S[h * QKDIM + e];
    }
    float tq = fminf(fmaxf(temp_q[h], 0.1f), 2.0f);
    float itq = 1.0f / tq;
    __syncthreads();

    // q logits
    {
        int e_me = tid & 127, r0 = tid >> 7;
        for (int r = r0; r < 32; r += 2) {
            const float* xr = xm + (size_t)(row0 + r) * DMODEL + h * DHEAD;
            float a = 0.f;
#pragma unroll
            for (int d = 0; d < 32; d++) a += xr[d] * wq_s[d][e_me];
            qs[r][e_me] = a * itq;
        }
    }
    __syncthreads();
    // row softmax over 128: 8 threads/row, 16 elems each
    {
        int r = tid >> 3, sub = tid & 7;
        float mx = -1e30f;
#pragma unroll
        for (int k = 0; k < 16; k++) mx = fmaxf(mx, qs[r][sub + (k << 3)]);
#pragma unroll
        for (int o = 4; o > 0; o >>= 1) mx = fmaxf(mx, __shfl_xor_sync(0xffffffffu, mx, o));
        float ev[16];
        float sm = 0.f;
#pragma unroll
        for (int k = 0; k < 16; k++) { ev[k] = expf(qs[r][sub + (k << 3)] - mx); sm += ev[k]; }
#pragma unroll
        for (int o = 4; o > 0; o >>= 1) sm += __shfl_xor_sync(0xffffffffu, sm, o);
        float inv = 1.0f / sm;
#pragma unroll
        for (int k = 0; k < 16; k++) qs[r][sub + (k << 3)] = ev[k] * inv;
    }
    __syncthreads();
    // qkv = q @ kv_s  -> out[n, h*32+c]
    {
        int c = tid & 31, rb = (tid >> 5) * 4;
        float a0 = 0.f, a1 = 0.f, a2 = 0.f, a3 = 0.f;
        for (int e = 0; e < 128; e++) {
            float kvv = kv_s[e][c];
            a0 += qs[rb + 0][e] * kvv;
            a1 += qs[rb + 1][e] * kvv;
            a2 += qs[rb + 2][e] * kvv;
            a3 += qs[rb + 3][e] * kvv;
        }
        out[(size_t)(row0 + rb + 0) * DMODEL + h * DHEAD + c] = a0;
        out[(size_t)(row0 + rb + 1) * DMODEL + h * DHEAD + c] = a1;
        out[(size_t)(row0 + rb + 2) * DMODEL + h * DHEAD + c] = a2;
        out[(size_t)(row0 + rb + 3) * DMODEL + h * DHEAD + c] = a3;
    }
}

// ---------------- head: out[n] = LN(fx) @ head_w + head_b ----------------
__global__ void head_kernel(const float* __restrict__ fx, const float* __restrict__ g,
                            const float* __restrict__ b, const float* __restrict__ hw,
                            const float* __restrict__ hb, float* __restrict__ out) {
    __shared__ float sh[8];
    int n = blockIdx.x, t = threadIdx.x;
    float v = fx[(size_t)n * DMODEL + t];
    float mean = block_sum256(v, sh) * (1.0f / DMODEL);
    float d = v - mean;
    float var = block_sum256(d * d, sh) * (1.0f / DMODEL);
    float rstd = rsqrtf(var + 1e-5f);
    float hn = d * rstd * g[t] + b[t];
    float dot = block_sum256(hn * hw[t], sh);
    if (t == 0) out[n] = dot + hb[0];
}

// ---------------- launch ----------------
extern "C" void kernel_launch(void* const* d_in, const int* in_sizes, int n_in,
                              void* d_out, int out_size) {
    const float* x          = (const float*)d_in[0];
    const float* pre_w1     = (const float*)d_in[1];
    const float* pre_b1     = (const float*)d_in[2];
    const float* pre_w2     = (const float*)d_in[3];
    const float* pre_b2     = (const float*)d_in[4];
    const float* placeholder= (const float*)d_in[5];
    const float* ln1_g      = (const float*)d_in[6];
    const float* ln1_b      = (const float*)d_in[7];
    const float* inp_w      = (const float*)d_in[8];
    const float* inp_b      = (const float*)d_in[9];
    const float* temp_q     = (const float*)d_in[10];
    const float* temp_k     = (const float*)d_in[11];
    const float* wq         = (const float*)d_in[12];
    const float* wk         = (const float*)d_in[13];
    const float* wv         = (const float*)d_in[14];
    const float* out_w1     = (const float*)d_in[15];
    const float* out_b1     = (const float*)d_in[16];
    const float* out_w2     = (const float*)d_in[17];
    const float* out_b2     = (const float*)d_in[18];
    const float* ln2_g      = (const float*)d_in[19];
    const float* ln2_b      = (const float*)d_in[20];
    const float* mlp_w1     = (const float*)d_in[21];
    const float* mlp_b1     = (const float*)d_in[22];
    const float* mlp_w2     = (const float*)d_in[23];
    const float* mlp_b2     = (const float*)d_in[24];
    const float* ln3_g      = (const float*)d_in[25];
    const float* ln3_b      = (const float*)d_in[26];
    const float* head_w     = (const float*)d_in[27];
    const float* head_b     = (const float*)d_in[28];

    float *fx, *t1, *t2, *t3, *hidden;
    cudaGetSymbolAddress((void**)&fx, g_fx);
    cudaGetSymbolAddress((void**)&t1, g_t1);
    cudaGetSymbolAddress((void**)&t2, g_t2);
    cudaGetSymbolAddress((void**)&t3, g_t3);
    cudaGetSymbolAddress((void**)&hidden, g_hidden);

    dim3 ggrid(NPTS / TBM, DMODEL / TBN);

    // preprocess
    pre1_kernel<<<NPTS * 512 / 256, 256>>>(x, pre_w1, pre_b1, hidden);
    gemm_kernel<<<ggrid, 256>>>(hidden, 512, pre_w2, pre_b2, placeholder, nullptr, fx, 0);

    for (int i = 0; i < NLAYERS; i++) {
        const float* iw  = inp_w + (size_t)i * 65536;
        const float* ow1 = out_w1 + (size_t)i * 65536;
        const float* ow2 = out_w2 + (size_t)i * 65536;
        const float* mw1 = mlp_w1 + (size_t)i * 65536;
        const float* mw2 = mlp_w2 + (size_t)i * 65536;

        ln_kernel<<<NPTS, 256>>>(fx, ln1_g + i * 256, ln1_b + i * 256, t1);
        gemm_kernel<<<ggrid, 256>>>(t1, 256, iw, inp_b + i * 256, nullptr, nullptr, t2, 0);
        zero_kv_kernel<<<(NH * QKDIM * DHEAD + 255) / 256, 256>>>();
        kv_kernel<<<dim3(64, NH), 256>>>(t2, wk + (size_t)i * 4096, wv + (size_t)i * 1024,
                                         temp_k + i * NH);
        qkv_kernel<<<dim3(NPTS / 32, NH), 256>>>(t2, wq + (size_t)i * 4096, temp_q + i * NH, t3);
        gemm_kernel<<<ggrid, 256>>>(t3, 256, ow1, out_b1 + i * 256, nullptr, nullptr, t1, 1);
        gemm_kernel<<<ggrid, 256>>>(t1, 256, ow2, out_b2 + i * 256, nullptr, fx, fx, 0);
        ln_kernel<<<NPTS, 256>>>(fx, ln2_g + i * 256, ln2_b + i * 256, t1);
        gemm_kernel<<<ggrid, 256>>>(t1, 256, mw1, mlp_b1 + i * 256, nullptr, nullptr, t2, 1);
        gemm_kernel<<<ggrid, 256>>>(t2, 256, mw2, mlp_b2 + i * 256, nullptr, fx, fx, 0);
    }
    head_kernel<<<NPTS, 256>>>(fx, ln3_g, ln3_b, head_w, head_b, (float*)d_out);
}

// round 3
// speedup vs baseline: 2.5032x; 1.6593x over previous
#include <cuda_runtime.h>
#include <math.h>
#include <stdint.h>

#define NPTS 32768
#define DMODEL 256
#define NH 8
#define DHEAD 32
#define QKDIM 128
#define NLAYERS 5

// ---------------- static device scratch (no allocs allowed) ----------------
__device__ float g_fx[NPTS * DMODEL];
__device__ float g_t1[NPTS * DMODEL];
__device__ float g_t2[NPTS * DMODEL];
__device__ float g_t3[NPTS * DMODEL];
__device__ float g_hidden[NPTS * 512];
__device__ float g_kv2[NH * QKDIM * 40];   // [h][e][c], c=32 holds S

__device__ __forceinline__ float gelu_f(float x) {
    return 0.5f * x * (1.0f + erff(x * 0.70710678118654752f));
}

__device__ __forceinline__ float to_tf32(float x) {
    uint32_t u;
    asm("cvt.rna.tf32.f32 %0, %1;" : "=r"(u) : "f"(x));
    return __uint_as_float(u);
}

__device__ __forceinline__ void mma_tf32(float* c, const uint32_t* a, const uint32_t* b) {
    asm volatile(
        "mma.sync.aligned.m16n8k8.row.col.f32.tf32.tf32.f32 "
        "{%0,%1,%2,%3}, {%4,%5,%6,%7}, {%8,%9}, {%0,%1,%2,%3};\n"
        : "+f"(c[0]), "+f"(c[1]), "+f"(c[2]), "+f"(c[3])
        : "r"(a[0]), "r"(a[1]), "r"(a[2]), "r"(a[3]), "r"(b[0]), "r"(b[1]));
}

// block-wide sum for 256 threads; result broadcast to all threads
__device__ __forceinline__ float block_sum256(float v, volatile float* sh) {
    int lane = threadIdx.x & 31;
#pragma unroll
    for (int o = 16; o > 0; o >>= 1) v += __shfl_down_sync(0xffffffffu, v, o);
    if (lane == 0) sh[threadIdx.x >> 5] = v;
    __syncthreads();
    if (threadIdx.x < 32) {
        float r = (lane < 8) ? sh[lane] : 0.f;
#pragma unroll
        for (int o = 4; o > 0; o >>= 1) r += __shfl_down_sync(0xffffffffu, r, o);
        if (lane == 0) sh[0] = r;
    }
    __syncthreads();
    float out = sh[0];
    __syncthreads();
    return out;
}

// ---------------- preprocess: hidden = gelu(x @ pre_w1 + b1) ----------------
__global__ void pre1_kernel(const float* __restrict__ x, const float* __restrict__ w1,
                            const float* __restrict__ b1, float* __restrict__ hidden) {
    int idx = blockIdx.x * 256 + threadIdx.x;
    int n = idx >> 9, j = idx & 511;
    float x0 = x[n * 3 + 0], x1 = x[n * 3 + 1], x2 = x[n * 3 + 2];
    float a = x0 * w1[j] + x1 * w1[512 + j] + x2 * w1[1024 + j] + b1[j];
    hidden[idx] = gelu_f(a);
}

// ---------------- tf32 tensor-core GEMM (unchanged from R1) ----------------
#define TBM 128
#define TBN 128
#define TBK 32
__global__ __launch_bounds__(256, 2)
void gemm_kernel(const float* __restrict__ A, int K,
                 const float* __restrict__ W,
                 const float* __restrict__ bias,
                 const float* __restrict__ colbias,
                 const float* __restrict__ residual,
                 float* __restrict__ Y, int act) {
    __shared__ float As[TBM][TBK + 4];
    __shared__ float Bs[TBK][TBN + 8];

    int m0 = blockIdx.x * TBM;
    int n0 = blockIdx.y * TBN;
    int tid = threadIdx.x;
    int wid = tid >> 5, lane = tid & 31;
    int wm = (wid >> 2) * 64;
    int wn = (wid & 3) * 32;
    int lr = lane >> 2;
    int lc = lane & 3;

    float acc[4][4][4];
#pragma unroll
    for (int i = 0; i < 4; i++)
#pragma unroll
        for (int j = 0; j < 4; j++)
#pragma unroll
            for (int k = 0; k < 4; k++) acc[i][j][k] = 0.f;

    int a_r = tid >> 3;
    int a_kc = (tid & 7) * 4;
    int b_kr = tid >> 5;
    int b_nc = lane * 4;

    for (int k0 = 0; k0 < K; k0 += TBK) {
#pragma unroll
        for (int rr = 0; rr < 4; rr++) {
            int row = a_r + rr * 32;
            float4 v = *(const float4*)(A + (size_t)(m0 + row) * K + k0 + a_kc);
            float4 c4;
            c4.x = to_tf32(v.x); c4.y = to_tf32(v.y);
            c4.z = to_tf32(v.z); c4.w = to_tf32(v.w);
            *(float4*)(&As[row][a_kc]) = c4;
        }
#pragma unroll
        for (int kk = 0; kk < 4; kk++) {
            int krow = b_kr + kk * 8;
            float4 v = *(const float4*)(W + (size_t)(k0 + krow) * DMODEL + n0 + b_nc);
            float4 c4;
            c4.x = to_tf32(v.x); c4.y = to_tf32(v.y);
            c4.z = to_tf32(v.z); c4.w = to_tf32(v.w);
            *(float4*)(&Bs[krow][b_nc]) = c4;
        }
        __syncthreads();

#pragma unroll
        for (int ks = 0; ks < TBK; ks += 8) {
            uint32_t af[4][4], bf[4][2];
#pragma unroll
            for (int mt = 0; mt < 4; mt++) {
                int r = wm + mt * 16 + lr;
                int c = ks + lc;
                af[mt][0] = __float_as_uint(As[r][c]);
                af[mt][1] = __float_as_uint(As[r + 8][c]);
                af[mt][2] = __float_as_uint(As[r][c + 4]);
                af[mt][3] = __float_as_uint(As[r + 8][c + 4]);
            }
#pragma unroll
            for (int nt = 0; nt < 4; nt++) {
                int n = wn + nt * 8 + lr;
                int c = ks + lc;
                bf[nt][0] = __float_as_uint(Bs[c][n]);
                bf[nt][1] = __float_as_uint(Bs[c + 4][n]);
            }
#pragma unroll
            for (int mt = 0; mt < 4; mt++)
#pragma unroll
                for (int nt = 0; nt < 4; nt++)
                    mma_tf32(acc[mt][nt], af[mt], bf[nt]);
        }
        __syncthreads();
    }

#pragma unroll
    for (int mt = 0; mt < 4; mt++) {
        int row = m0 + wm + mt * 16 + lr;
#pragma unroll
        for (int nt = 0; nt < 4; nt++) {
            int col = n0 + wn + nt * 8 + lc * 2;
#pragma unroll
            for (int half = 0; half < 2; half++) {
                int r = row + half * 8;
                float v0 = acc[mt][nt][half * 2 + 0];
                float v1 = acc[mt][nt][half * 2 + 1];
                if (bias)    { v0 += bias[col];        v1 += bias[col + 1]; }
                if (colbias) { v0 += colbias[col];     v1 += colbias[col + 1]; }
                if (act)     { v0 = gelu_f(v0);        v1 = gelu_f(v1); }
                if (residual) {
                    v0 += residual[(size_t)r * DMODEL + col];
                    v1 += residual[(size_t)r * DMODEL + col + 1];
                }
                float2 o; o.x = v0; o.y = v1;
                *(float2*)(Y + (size_t)r * DMODEL + col) = o;
            }
        }
    }
}

// ---------------- LayerNorm (row-wise, D=256) ----------------
__global__ void ln_kernel(const float* __restrict__ X, const float* __restrict__ g,
                          const float* __restrict__ b, float* __restrict__ Y) {
    __shared__ float sh[8];
    int n = blockIdx.x, t = threadIdx.x;
    float v = X[(size_t)n * DMODEL + t];
    float mean = block_sum256(v, sh) * (1.0f / DMODEL);
    float d = v - mean;
    float var = block_sum256(d * d, sh) * (1.0f / DMODEL);
    float rstd = rsqrtf(var + 1e-5f);
    Y[(size_t)n * DMODEL + t] = d * rstd * g[t] + b[t];
}

// ---------------- zero kv accumulators ----------------
__global__ void zero_kv_kernel() {
    int idx = blockIdx.x * 256 + threadIdx.x;
    if (idx < NH * QKDIM * 40) g_kv2[idx] = 0.f;
}

// ================= tensor-core KV =================
// kv[h,e,c] = sum_n exp(k_logit/tk) * v[n,c];  col 32 accumulates S (ones col in v)
// grid (32, NH), 256 threads, 1024 rows/block in 16 chunks of 64.
#define KV_SMEM_FLOATS (32*136 + 32*44 + 64*36 + 128*68 + 64*44)
__global__ void kv_mma_kernel(const float* __restrict__ xm, const float* __restrict__ wk,
                              const float* __restrict__ wv, const float* __restrict__ temp_k,
                              float* __restrict__ kvout) {
    extern __shared__ float sm[];
    float* wk_s = sm;                   // [32][136]
    float* wv_s = wk_s + 32 * 136;      // [32][44]
    float* xm_s = wv_s + 32 * 44;       // [64][36]
    float* kT_s = xm_s + 64 * 36;       // [128][68]  (transposed exp(k))
    float* v_s  = kT_s + 128 * 68;      // [64][44]

    int h = blockIdx.y;
    int tid = threadIdx.x;
    int wid = tid >> 5, lane = tid & 31;
    int lr = lane >> 2, lc = lane & 3;

    for (int i = tid; i < 32 * 128; i += 256) {
        int k = i >> 7, e = i & 127;
        wk_s[k * 136 + e] = to_tf32(wk[k * 128 + e]);
    }
    for (int i = tid; i < 32 * 32; i += 256) {
        int k = i >> 5, c = i & 31;
        wv_s[k * 44 + c] = to_tf32(wv[k * 32 + c]);
    }
    float itk = 1.0f / fminf(fmaxf(temp_k[h], 0.1f), 2.0f);

    float kvacc[5][4];
#pragma unroll
    for (int i = 0; i < 5; i++)
#pragma unroll
        for (int j = 0; j < 4; j++) kvacc[i][j] = 0.f;

    int row0 = blockIdx.x * 1024;

    for (int ch = 0; ch < 16; ch++) {
        __syncthreads();
        {   // stage xm [64][32]
            int r = tid >> 2, c0 = (tid & 3) * 8;
            const float* src = xm + (size_t)(row0 + ch * 64 + r) * DMODEL + h * DHEAD + c0;
            float4 v1 = *(const float4*)src, v2 = *(const float4*)(src + 4);
            float* dst = &xm_s[r * 36 + c0];
            dst[0] = to_tf32(v1.x); dst[1] = to_tf32(v1.y);
            dst[2] = to_tf32(v1.z); dst[3] = to_tf32(v1.w);
            dst[4] = to_tf32(v2.x); dst[5] = to_tf32(v2.y);
            dst[6] = to_tf32(v2.z); dst[7] = to_tf32(v2.w);
        }
        __syncthreads();

        {   // logits MMA: [64 x 128] = xm @ wk ; 8 warps 4m x 2n
            int wm = (wid & 3) * 16, wn = (wid >> 2) * 64;
            float acc[8][4];
#pragma unroll
            for (int i = 0; i < 8; i++)
#pragma unroll
                for (int j = 0; j < 4; j++) acc[i][j] = 0.f;
#pragma unroll
            for (int ks = 0; ks < 32; ks += 8) {
                uint32_t a[4];
                a[0] = __float_as_uint(xm_s[(wm + lr) * 36 + ks + lc]);
                a[1] = __float_as_uint(xm_s[(wm + lr + 8) * 36 + ks + lc]);
                a[2] = __float_as_uint(xm_s[(wm + lr) * 36 + ks + lc + 4]);
                a[3] = __float_as_uint(xm_s[(wm + lr + 8) * 36 + ks + lc + 4]);
#pragma unroll
                for (int nt = 0; nt < 8; nt++) {
                    uint32_t b[2];
                    b[0] = __float_as_uint(wk_s[(ks + lc) * 136 + wn + nt * 8 + lr]);
                    b[1] = __float_as_uint(wk_s[(ks + lc + 4) * 136 + wn + nt * 8 + lr]);
                    mma_tf32(acc[nt], a, b);
                }
            }
            // exp + transposed store
#pragma unroll
            for (int nt = 0; nt < 8; nt++) {
                int col = wn + nt * 8 + 2 * lc;
                int r = wm + lr;
                kT_s[col * 68 + r]           = to_tf32(__expf(acc[nt][0] * itk));
                kT_s[(col + 1) * 68 + r]     = to_tf32(__expf(acc[nt][1] * itk));
                kT_s[col * 68 + r + 8]       = to_tf32(__expf(acc[nt][2] * itk));
                kT_s[(col + 1) * 68 + r + 8] = to_tf32(__expf(acc[nt][3] * itk));
            }
        }
        if (wid < 4) {  // v MMA: [64 x 32] = xm @ wv ; 4 warps
            int wm = wid * 16;
            float acc[4][4];
#pragma unroll
            for (int i = 0; i < 4; i++)
#pragma unroll
                for (int j = 0; j < 4; j++) acc[i][j] = 0.f;
#pragma unroll
            for (int ks = 0; ks < 32; ks += 8) {
                uint32_t a[4];
                a[0] = __float_as_uint(xm_s[(wm + lr) * 36 + ks + lc]);
                a[1] = __float_as_uint(xm_s[(wm + lr + 8) * 36 + ks + lc]);
                a[2] = __float_as_uint(xm_s[(wm + lr) * 36 + ks + lc + 4]);
                a[3] = __float_as_uint(xm_s[(wm + lr + 8) * 36 + ks + lc + 4]);
#pragma unroll
                for (int nt = 0; nt < 4; nt++) {
                    uint32_t b[2];
                    b[0] = __float_as_uint(wv_s[(ks + lc) * 44 + nt * 8 + lr]);
                    b[1] = __float_as_uint(wv_s[(ks + lc + 4) * 44 + nt * 8 + lr]);
                    mma_tf32(acc[nt], a, b);
                }
            }
#pragma unroll
            for (int nt = 0; nt < 4; nt++) {
                int col = nt * 8 + 2 * lc;
                int r = wm + lr;
                v_s[r * 44 + col]           = to_tf32(acc[nt][0]);
                v_s[r * 44 + col + 1]       = to_tf32(acc[nt][1]);
                v_s[(r + 8) * 44 + col]     = to_tf32(acc[nt][2]);
                v_s[(r + 8) * 44 + col + 1] = to_tf32(acc[nt][3]);
            }
        }
        if (tid < 64) v_s[tid * 44 + 32] = 1.0f;  // ones col -> S
        __syncthreads();

        {   // kv += kT[128 x 64] @ v[64 x 40] ; warp e-tile = wid*16
            int we = wid * 16;
#pragma unroll
            for (int ks = 0; ks < 64; ks += 8) {
                uint32_t a[4];
                a[0] = __float_as_uint(kT_s[(we + lr) * 68 + ks + lc]);
                a[1] = __float_as_uint(kT_s[(we + lr + 8) * 68 + ks + lc]);
                a[2] = __float_as_uint(kT_s[(we + lr) * 68 + ks + lc + 4]);
                a[3] = __float_as_uint(kT_s[(we + lr + 8) * 68 + ks + lc + 4]);
#pragma unroll
                for (int nt = 0; nt < 5; nt++) {
                    uint32_t b[2];
                    b[0] = __float_as_uint(v_s[(ks + lc) * 44 + nt * 8 + lr]);
                    b[1] = __float_as_uint(v_s[(ks + lc + 4) * 44 + nt * 8 + lr]);
                    mma_tf32(kvacc[nt], a, b);
                }
            }
        }
    }
    // flush accumulators (cols <= 32 only)
    {
        int we = wid * 16;
#pragma unroll
        for (int nt = 0; nt < 5; nt++) {
            int col = nt * 8 + 2 * lc;
            int e0 = we + lr, e1 = we + lr + 8;
            if (col <= 32) {
                atomicAdd(&kvout[(h * QKDIM + e0) * 40 + col], kvacc[nt][0]);
                atomicAdd(&kvout[(h * QKDIM + e1) * 40 + col], kvacc[nt][2]);
            }
            if (col + 1 <= 32) {
                atomicAdd(&kvout[(h * QKDIM + e0) * 40 + col + 1], kvacc[nt][1]);
                atomicAdd(&kvout[(h * QKDIM + e1) * 40 + col + 1], kvacc[nt][3]);
            }
        }
    }
}

// ================= tensor-core QKV =================
// q = softmax((xm@wq)/tq) over e; out = q @ (kv/S), kv hi/lo split for accuracy.
// grid (512, NH), 64 rows/block, 256 threads.
#define QKV_SMEM_FLOATS (128*36*2 + 32*136 + 64*36 + 64*132)
__global__ void qkv_mma_kernel(const float* __restrict__ xm, const float* __restrict__ wq,
                               const float* __restrict__ temp_q, const float* __restrict__ kv2,
                               float* __restrict__ out) {
    extern __shared__ float sm[];
    float* kvh  = sm;                    // [128][36]
    float* kvl  = kvh + 128 * 36;        // [128][36]
    float* wq_s = kvl + 128 * 36;        // [32][136]
    float* xm_s = wq_s + 32 * 136;       // [64][36]  (reused as partial-out later)
    float* q_s  = xm_s + 64 * 36;        // [64][132]

    int h = blockIdx.y;
    int row0 = blockIdx.x * 64;
    int tid = threadIdx.x;
    int wid = tid >> 5, lane = tid & 31;
    int lr = lane >> 2, lc = lane & 3;

    for (int i = tid; i < 32 * 128; i += 256) {
        int k = i >> 7, e = i & 127;
        wq_s[k * 136 + e] = to_tf32(wq[k * 128 + e]);
    }
    for (int i = tid; i < 128 * 32; i += 256) {
        int e = i >> 5, c = i & 31;
        float kvv = kv2[(h * QKDIM + e) * 40 + c] / kv2[(h * QKDIM + e) * 40 + 32];
        float hi = to_tf32(kvv);
        kvh[e * 36 + c] = hi;
        kvl[e * 36 + c] = to_tf32(kvv - hi);
    }
    {   // stage xm [64][32]
        int r = tid >> 2, c0 = (tid & 3) * 8;
        const float* src = xm + (size_t)(row0 + r) * DMODEL + h * DHEAD + c0;
        float4 v1 = *(const float4*)src, v2 = *(const float4*)(src + 4);
        float* dst = &xm_s[r * 36 + c0];
        dst[0] = to_tf32(v1.x); dst[1] = to_tf32(v1.y);
        dst[2] = to_tf32(v1.z); dst[3] = to_tf32(v1.w);
        dst[4] = to_tf32(v2.x); dst[5] = to_tf32(v2.y);
        dst[6] = to_tf32(v2.z); dst[7] = to_tf32(v2.w);
    }
    float itq = 1.0f / fminf(fmaxf(temp_q[h], 0.1f), 2.0f);
    __syncthreads();

    {   // logits MMA: [64 x 128] = xm @ wq, scaled by itq -> q_s
        int wm = (wid & 3) * 16, wn = (wid >> 2) * 64;
        float acc[8][4];
#pragma unroll
        for (int i = 0; i < 8; i++)
#pragma unroll
            for (int j = 0; j < 4; j++) acc[i][j] = 0.f;
#pragma unroll
        for (int ks = 0; ks < 32; ks += 8) {
            uint32_t a[4];
            a[0] = __float_as_uint(xm_s[(wm + lr) * 36 + ks + lc]);
            a[1] = __float_as_uint(xm_s[(wm + lr + 8) * 36 + ks + lc]);
            a[2] = __float_as_uint(xm_s[(wm + lr) * 36 + ks + lc + 4]);
            a[3] = __float_as_uint(xm_s[(wm + lr + 8) * 36 + ks + lc + 4]);
#pragma unroll
            for (int nt = 0; nt < 8; nt++) {
                uint32_t b[2];
                b[0] = __float_as_uint(wq_s[(ks + lc) * 136 + wn + nt * 8 + lr]);
                b[1] = __float_as_uint(wq_s[(ks + lc + 4) * 136 + wn + nt * 8 + lr]);
                mma_tf32(acc[nt], a, b);
            }
        }
#pragma unroll
        for (int nt = 0; nt < 8; nt++) {
            int col = wn + nt * 8 + 2 * lc;
            int r = wm + lr;
            q_s[r * 132 + col]           = acc[nt][0] * itq;
            q_s[r * 132 + col + 1]       = acc[nt][1] * itq;
            q_s[(r + 8) * 132 + col]     = acc[nt][2] * itq;
            q_s[(r + 8) * 132 + col + 1] = acc[nt][3] * itq;
        }
    }
    __syncthreads();
    {   // row softmax over 128; 4 threads/row, 32 elems each (stride 4)
        int r = tid >> 2, sub = tid & 3;
        float* row = q_s + r * 132;
        float mx = -1e30f;
#pragma unroll
        for (int k = 0; k < 32; k++) mx = fmaxf(mx, row[sub + k * 4]);
        mx = fmaxf(mx, __shfl_xor_sync(0xffffffffu, mx, 1));
        mx = fmaxf(mx, __shfl_xor_sync(0xffffffffu, mx, 2));
        float ev[32], sum = 0.f;
#pragma unroll
        for (int k = 0; k < 32; k++) { ev[k] = __expf(row[sub + k * 4] - mx); sum += ev[k]; }
        sum += __shfl_xor_sync(0xffffffffu, sum, 1);
        sum += __shfl_xor_sync(0xffffffffu, sum, 2);
        float inv = 1.0f / sum;
#pragma unroll
        for (int k = 0; k < 32; k++) row[sub + k * 4] = to_tf32(ev[k] * inv);
    }
    __syncthreads();
    {   // out = q[64x128] @ kv[128x32]; warps 0-3: hi part, 4-7: lo part
        int wm = (wid & 3) * 16;
        int part = wid >> 2;
        const float* kvp = part ? kvl : kvh;
        float acc[4][4];
#pragma unroll
        for (int i = 0; i < 4; i++)
#pragma unroll
            for (int j = 0; j < 4; j++) acc[i][j] = 0.f;
#pragma unroll
        for (int ks = 0; ks < 128; ks += 8) {
            uint32_t a[4];
            a[0] = __float_as_uint(q_s[(wm + lr) * 132 + ks + lc]);
            a[1] = __float_as_uint(q_s[(wm + lr + 8) * 132 + ks + lc]);
            a[2] = __float_as_uint(q_s[(wm + lr) * 132 + ks + lc + 4]);
            a[3] = __float_as_uint(q_s[(wm + lr + 8) * 132 + ks + lc + 4]);
#pragma unroll
            for (int nt = 0; nt < 4; nt++) {
                uint32_t b[2];
                b[0] = __float_as_uint(kvp[(ks + lc) * 36 + nt * 8 + lr]);
                b[1] = __float_as_uint(kvp[(ks + lc + 4) * 36 + nt * 8 + lr]);
                mma_tf32(acc[nt], a, b);
            }
        }
        if (part == 1) {  // lo partials -> xm_s (dead)
#pragma unroll
            for (int nt = 0; nt < 4; nt++) {
                int col = nt * 8 + 2 * lc;
                int r = wm + lr;
                xm_s[r * 36 + col]           = acc[nt][0];
                xm_s[r * 36 + col + 1]       = acc[nt][1];
                xm_s[(r + 8) * 36 + col]     = acc[nt][2];
                xm_s[(r + 8) * 36 + col + 1] = acc[nt][3];
            }
        }
        __syncthreads();
        if (part == 0) {
#pragma unroll
            for (int nt = 0; nt < 4; nt++) {
                int col = nt * 8 + 2 * lc;
#pragma unroll
                for (int half = 0; half < 2; half++) {
                    int r = wm + lr + half * 8;
                    float v0 = acc[nt][half * 2 + 0] + xm_s[r * 36 + col];
                    float v1 = acc[nt][half * 2 + 1] + xm_s[r * 36 + col + 1];
                    float2 o; o.x = v0; o.y = v1;
                    *(float2*)(out + (size_t)(row0 + r) * DMODEL + h * DHEAD + col) = o;
                }
            }
        }
    }
}

// ---------------- head: out[n] = LN(fx) @ head_w + head_b ----------------
__global__ void head_kernel(const float* __restrict__ fx, const float* __restrict__ g,
                            const float* __restrict__ b, const float* __restrict__ hw,
                            const float* __restrict__ hb, float* __restrict__ out) {
    __shared__ float sh[8];
    int n = blockIdx.x, t = threadIdx.x;
    float v = fx[(size_t)n * DMODEL + t];
    float mean = block_sum256(v, sh) * (1.0f / DMODEL);
    float d = v - mean;
    float var = block_sum256(d * d, sh) * (1.0f / DMODEL);
    float rstd = rsqrtf(var + 1e-5f);
    float hn = d * rstd * g[t] + b[t];
    float dot = block_sum256(hn * hw[t], sh);
    if (t == 0) out[n] = dot + hb[0];
}

// ---------------- launch ----------------
extern "C" void kernel_launch(void* const* d_in, const int* in_sizes, int n_in,
                              void* d_out, int out_size) {
    const float* x          = (const float*)d_in[0];
    const float* pre_w1     = (const float*)d_in[1];
    const float* pre_b1     = (const float*)d_in[2];
    const float* pre_w2     = (const float*)d_in[3];
    const float* pre_b2     = (const float*)d_in[4];
    const float* placeholder= (const float*)d_in[5];
    const float* ln1_g      = (const float*)d_in[6];
    const float* ln1_b      = (const float*)d_in[7];
    const float* inp_w      = (const float*)d_in[8];
    const float* inp_b      = (const float*)d_in[9];
    const float* temp_q     = (const float*)d_in[10];
    const float* temp_k     = (const float*)d_in[11];
    const float* wq         = (const float*)d_in[12];
    const float* wk         = (const float*)d_in[13];
    const float* wv         = (const float*)d_in[14];
    const float* out_w1     = (const float*)d_in[15];
    const float* out_b1     = (const float*)d_in[16];
    const float* out_w2     = (const float*)d_in[17];
    const float* out_b2     = (const float*)d_in[18];
    const float* ln2_g      = (const float*)d_in[19];
    const float* ln2_b      = (const float*)d_in[20];
    const float* mlp_w1     = (const float*)d_in[21];
    const float* mlp_b1     = (const float*)d_in[22];
    const float* mlp_w2     = (const float*)d_in[23];
    const float* mlp_b2     = (const float*)d_in[24];
    const float* ln3_g      = (const float*)d_in[25];
    const float* ln3_b      = (const float*)d_in[26];
    const float* head_w     = (const float*)d_in[27];
    const float* head_b     = (const float*)d_in[28];

    float *fx, *t1, *t2, *t3, *hidden, *kv2;
    cudaGetSymbolAddress((void**)&fx, g_fx);
    cudaGetSymbolAddress((void**)&t1, g_t1);
    cudaGetSymbolAddress((void**)&t2, g_t2);
    cudaGetSymbolAddress((void**)&t3, g_t3);
    cudaGetSymbolAddress((void**)&hidden, g_hidden);
    cudaGetSymbolAddress((void**)&kv2, g_kv2);

    const int kv_smem = KV_SMEM_FLOATS * 4;
    const int qkv_smem = QKV_SMEM_FLOATS * 4;
    cudaFuncSetAttribute(kv_mma_kernel, cudaFuncAttributeMaxDynamicSharedMemorySize, kv_smem);
    cudaFuncSetAttribute(qkv_mma_kernel, cudaFuncAttributeMaxDynamicSharedMemorySize, qkv_smem);

    dim3 ggrid(NPTS / TBM, DMODEL / TBN);

    pre1_kernel<<<NPTS * 512 / 256, 256>>>(x, pre_w1, pre_b1, hidden);
    gemm_kernel<<<ggrid, 256>>>(hidden, 512, pre_w2, pre_b2, placeholder, nullptr, fx, 0);

    for (int i = 0; i < NLAYERS; i++) {
        const float* iw  = inp_w + (size_t)i * 65536;
        const float* ow1 = out_w1 + (size_t)i * 65536;
        const float* ow2 = out_w2 + (size_t)i * 65536;
        const float* mw1 = mlp_w1 + (size_t)i * 65536;
        const float* mw2 = mlp_w2 + (size_t)i * 65536;

        ln_kernel<<<NPTS, 256>>>(fx, ln1_g + i * 256, ln1_b + i * 256, t1);
        gemm_kernel<<<ggrid, 256>>>(t1, 256, iw, inp_b + i * 256, nullptr, nullptr, t2, 0);
        zero_kv_kernel<<<(NH * QKDIM * 40 + 255) / 256, 256>>>();
        kv_mma_kernel<<<dim3(32, NH), 256, kv_smem>>>(t2, wk + (size_t)i * 4096,
                                                      wv + (size_t)i * 1024, temp_k + i * NH, kv2);
        qkv_mma_kernel<<<dim3(NPTS / 64, NH), 256, qkv_smem>>>(t2, wq + (size_t)i * 4096,
                                                               temp_q + i * NH, kv2, t3);
        gemm_kernel<<<ggrid, 256>>>(t3, 256, ow1, out_b1 + i * 256, nullptr, nullptr, t1, 1);
        gemm_kernel<<<ggrid, 256>>>(t1, 256, ow2, out_b2 + i * 256, nullptr, fx, fx, 0);
        ln_kernel<<<NPTS, 256>>>(fx, ln2_g + i * 256, ln2_b + i * 256, t1);
        gemm_kernel<<<ggrid, 256>>>(t1, 256, mw1, mlp_b1 + i * 256, nullptr, nullptr, t2, 1);
        gemm_kernel<<<ggrid, 256>>>(t2, 256, mw2, mlp_b2 + i * 256, nullptr, fx, fx, 0);
    }
    head_kernel<<<NPTS, 256>>>(fx, ln3_g, ln3_b, head_w, head_b, (float*)d_out);
}

// round 4
// speedup vs baseline: 2.7587x; 1.1021x over previous
#include <cuda_runtime.h>
#include <math.h>
#include <stdint.h>

#define NPTS 32768
#define DMODEL 256
#define NH 8
#define DHEAD 32
#define QKDIM 128
#define NLAYERS 5

// ---------------- static device scratch (no allocs allowed) ----------------
__device__ float g_fx[NPTS * DMODEL];
__device__ float g_t1[NPTS * DMODEL];
__device__ float g_t2[NPTS * DMODEL];
__device__ float g_t3[NPTS * DMODEL];
__device__ float g_hidden[NPTS * 512];
__device__ float g_kv2[NH * QKDIM * 40];   // [h][e][c], c=32 holds S

__device__ __forceinline__ float gelu_f(float x) {
    return 0.5f * x * (1.0f + erff(x * 0.70710678118654752f));
}

__device__ __forceinline__ float to_tf32(float x) {
    uint32_t u;
    asm("cvt.rna.tf32.f32 %0, %1;" : "=r"(u) : "f"(x));
    return __uint_as_float(u);
}

__device__ __forceinline__ uint32_t to_tf32_u(float x) {
    uint32_t u;
    asm("cvt.rna.tf32.f32 %0, %1;" : "=r"(u) : "f"(x));
    return u;
}

__device__ __forceinline__ void mma_tf32(float* c, const uint32_t* a, const uint32_t* b) {
    asm volatile(
        "mma.sync.aligned.m16n8k8.row.col.f32.tf32.tf32.f32 "
        "{%0,%1,%2,%3}, {%4,%5,%6,%7}, {%8,%9}, {%0,%1,%2,%3};\n"
        : "+f"(c[0]), "+f"(c[1]), "+f"(c[2]), "+f"(c[3])
        : "r"(a[0]), "r"(a[1]), "r"(a[2]), "r"(a[3]), "r"(b[0]), "r"(b[1]));
}

__device__ __forceinline__ void cpa16(float* dst, const float* src) {
    uint32_t d = (uint32_t)__cvta_generic_to_shared(dst);
    asm volatile("cp.async.cg.shared.global [%0], [%1], 16;\n" :: "r"(d), "l"(src));
}

// block-wide sum for 256 threads; result broadcast to all threads
__device__ __forceinline__ float block_sum256(float v, volatile float* sh) {
    int lane = threadIdx.x & 31;
#pragma unroll
    for (int o = 16; o > 0; o >>= 1) v += __shfl_down_sync(0xffffffffu, v, o);
    if (lane == 0) sh[threadIdx.x >> 5] = v;
    __syncthreads();
    if (threadIdx.x < 32) {
        float r = (lane < 8) ? sh[lane] : 0.f;
#pragma unroll
        for (int o = 4; o > 0; o >>= 1) r += __shfl_down_sync(0xffffffffu, r, o);
        if (lane == 0) sh[0] = r;
    }
    __syncthreads();
    float out = sh[0];
    __syncthreads();
    return out;
}

// ---------------- preprocess: hidden = gelu(x @ pre_w1 + b1) ----------------
__global__ void pre1_kernel(const float* __restrict__ x, const float* __restrict__ w1,
                            const float* __restrict__ b1, float* __restrict__ hidden) {
    int idx = blockIdx.x * 256 + threadIdx.x;
    int n = idx >> 9, j = idx & 511;
    float x0 = x[n * 3 + 0], x1 = x[n * 3 + 1], x2 = x[n * 3 + 2];
    float a = x0 * w1[j] + x1 * w1[512 + j] + x2 * w1[1024 + j] + b1[j];
    hidden[idx] = gelu_f(a);
}

// ---------------- tf32 tensor-core GEMM, cp.async double-buffered ----------------
// Y[N,256] = act(A[N,K] @ W[K,256] + bias + colbias) + residual
#define TBM 128
#define TBN 128
#define TBK 32
#define AS_STRIDE 36
#define BS_STRIDE 136
#define AS_FLOATS (TBM * AS_STRIDE)          // 4608
#define BS_FLOATS (TBK * BS_STRIDE)          // 4352
#define GEMM_SMEM_FLOATS (2 * (AS_FLOATS + BS_FLOATS))
__global__ __launch_bounds__(256, 2)
void gemm_kernel(const float* __restrict__ A, int K,
                 const float* __restrict__ W,
                 const float* __restrict__ bias,
                 const float* __restrict__ colbias,
                 const float* __restrict__ residual,
                 float* __restrict__ Y, int act) {
    extern __shared__ float smem[];
    float* As = smem;                          // [2][128][36]
    float* Bs = smem + 2 * AS_FLOATS;          // [2][32][136]

    int m0 = blockIdx.x * TBM;
    int n0 = blockIdx.y * TBN;
    int tid = threadIdx.x;
    int wid = tid >> 5, lane = tid & 31;
    int wm = (wid >> 2) * 64;
    int wn = (wid & 3) * 32;
    int lr = lane >> 2;
    int lc = lane & 3;

    float acc[4][4][4];
#pragma unroll
    for (int i = 0; i < 4; i++)
#pragma unroll
        for (int j = 0; j < 4; j++)
#pragma unroll
            for (int k = 0; k < 4; k++) acc[i][j][k] = 0.f;

    int a_r = tid >> 3;            // 0..31
    int a_kc = (tid & 7) * 4;      // k offset
    int b_kr = tid >> 5;           // 0..7
    int b_nc = lane * 4;           // 0..124

    int nit = K / TBK;

    // prefetch stage 0
    {
        float* as = As;
        float* bs = Bs;
#pragma unroll
        for (int rr = 0; rr < 4; rr++) {
            int row = a_r + rr * 32;
            cpa16(&as[row * AS_STRIDE + a_kc], A + (size_t)(m0 + row) * K + a_kc);
        }
#pragma unroll
        for (int kk = 0; kk < 4; kk++) {
            int krow = b_kr + kk * 8;
            cpa16(&bs[krow * BS_STRIDE + b_nc], W + (size_t)krow * DMODEL + n0 + b_nc);
        }
        asm volatile("cp.async.commit_group;\n");
    }

    for (int it = 0; it < nit; it++) {
        int cur = it & 1;
        if (it + 1 < nit) {
            int nxt = (it + 1) & 1;
            int k0 = (it + 1) * TBK;
            float* as = As + nxt * AS_FLOATS;
            float* bs = Bs + nxt * BS_FLOATS;
#pragma unroll
            for (int rr = 0; rr < 4; rr++) {
                int row = a_r + rr * 32;
                cpa16(&as[row * AS_STRIDE + a_kc], A + (size_t)(m0 + row) * K + k0 + a_kc);
            }
#pragma unroll
            for (int kk = 0; kk < 4; kk++) {
                int krow = b_kr + kk * 8;
                cpa16(&bs[krow * BS_STRIDE + b_nc], W + (size_t)(k0 + krow) * DMODEL + n0 + b_nc);
            }
            asm volatile("cp.async.commit_group;\n");
            asm volatile("cp.async.wait_group 1;\n");
        } else {
            asm volatile("cp.async.wait_group 0;\n");
        }
        __syncthreads();

        const float* as = As + cur * AS_FLOATS;
        const float* bs = Bs + cur * BS_FLOATS;
#pragma unroll
        for (int ks = 0; ks < TBK; ks += 8) {
            uint32_t af[4][4], bf[4][2];
#pragma unroll
            for (int mt = 0; mt < 4; mt++) {
                int r = wm + mt * 16 + lr;
                int c = ks + lc;
                af[mt][0] = to_tf32_u(as[r * AS_STRIDE + c]);
                af[mt][1] = to_tf32_u(as[(r + 8) * AS_STRIDE + c]);
                af[mt][2] = to_tf32_u(as[r * AS_STRIDE + c + 4]);
                af[mt][3] = to_tf32_u(as[(r + 8) * AS_STRIDE + c + 4]);
            }
#pragma unroll
            for (int nt = 0; nt < 4; nt++) {
                int n = wn + nt * 8 + lr;
                int c = ks + lc;
                bf[nt][0] = to_tf32_u(bs[c * BS_STRIDE + n]);
                bf[nt][1] = to_tf32_u(bs[(c + 4) * BS_STRIDE + n]);
            }
#pragma unroll
            for (int mt = 0; mt < 4; mt++)
#pragma unroll
                for (int nt = 0; nt < 4; nt++)
                    mma_tf32(acc[mt][nt], af[mt], bf[nt]);
        }
        __syncthreads();
    }

#pragma unroll
    for (int mt = 0; mt < 4; mt++) {
        int row = m0 + wm + mt * 16 + lr;
#pragma unroll
        for (int nt = 0; nt < 4; nt++) {
            int col = n0 + wn + nt * 8 + lc * 2;
#pragma unroll
            for (int half = 0; half < 2; half++) {
                int r = row + half * 8;
                float v0 = acc[mt][nt][half * 2 + 0];
                float v1 = acc[mt][nt][half * 2 + 1];
                if (bias)    { v0 += bias[col];        v1 += bias[col + 1]; }
                if (colbias) { v0 += colbias[col];     v1 += colbias[col + 1]; }
                if (act)     { v0 = gelu_f(v0);        v1 = gelu_f(v1); }
                if (residual) {
                    v0 += residual[(size_t)r * DMODEL + col];
                    v1 += residual[(size_t)r * DMODEL + col + 1];
                }
                float2 o; o.x = v0; o.y = v1;
                *(float2*)(Y + (size_t)r * DMODEL + col) = o;
            }
        }
    }
}

// ---------------- LayerNorm: warp per row, single pass ----------------
__global__ void ln_kernel(const float* __restrict__ X, const float* __restrict__ g,
                          const float* __restrict__ b, float* __restrict__ Y) {
    int wid = threadIdx.x >> 5, lane = threadIdx.x & 31;
    int row = blockIdx.x * 8 + wid;
    const float4* X4 = (const float4*)(X + (size_t)row * DMODEL);
    const float4* G4 = (const float4*)g;
    const float4* B4 = (const float4*)b;
    float4* Y4 = (float4*)(Y + (size_t)row * DMODEL);

    float4 a = X4[lane];
    float4 c = X4[lane + 32];
    float s = a.x + a.y + a.z + a.w + c.x + c.y + c.z + c.w;
    float q = a.x * a.x + a.y * a.y + a.z * a.z + a.w * a.w
            + c.x * c.x + c.y * c.y + c.z * c.z + c.w * c.w;
#pragma unroll
    for (int o = 16; o > 0; o >>= 1) {
        s += __shfl_xor_sync(0xffffffffu, s, o);
        q += __shfl_xor_sync(0xffffffffu, q, o);
    }
    float mean = s * (1.0f / DMODEL);
    float var = q * (1.0f / DMODEL) - mean * mean;
    float rstd = rsqrtf(fmaxf(var, 0.f) + 1e-5f);

    float4 g1 = G4[lane], g2 = G4[lane + 32];
    float4 b1 = B4[lane], b2 = B4[lane + 32];
    float4 o1, o2;
    o1.x = (a.x - mean) * rstd * g1.x + b1.x;
    o1.y = (a.y - mean) * rstd * g1.y + b1.y;
    o1.z = (a.z - mean) * rstd * g1.z + b1.z;
    o1.w = (a.w - mean) * rstd * g1.w + b1.w;
    o2.x = (c.x - mean) * rstd * g2.x + b2.x;
    o2.y = (c.y - mean) * rstd * g2.y + b2.y;
    o2.z = (c.z - mean) * rstd * g2.z + b2.z;
    o2.w = (c.w - mean) * rstd * g2.w + b2.w;
    Y4[lane] = o1;
    Y4[lane + 32] = o2;
}

// ---------------- zero kv accumulators ----------------
__global__ void zero_kv_kernel() {
    int idx = blockIdx.x * 256 + threadIdx.x;
    if (idx < NH * QKDIM * 40) g_kv2[idx] = 0.f;
}

// ================= tensor-core KV =================
#define KV_SMEM_FLOATS (32*136 + 32*44 + 64*36 + 128*68 + 64*44)
__global__ void kv_mma_kernel(const float* __restrict__ xm, const float* __restrict__ wk,
                              const float* __restrict__ wv, const float* __restrict__ temp_k,
                              float* __restrict__ kvout) {
    extern __shared__ float sm[];
    float* wk_s = sm;                   // [32][136]
    float* wv_s = wk_s + 32 * 136;      // [32][44]
    float* xm_s = wv_s + 32 * 44;       // [64][36]
    float* kT_s = xm_s + 64 * 36;       // [128][68]
    float* v_s  = kT_s + 128 * 68;      // [64][44]

    int h = blockIdx.y;
    int tid = threadIdx.x;
    int wid = tid >> 5, lane = tid & 31;
    int lr = lane >> 2, lc = lane & 3;

    for (int i = tid; i < 32 * 128; i += 256) {
        int k = i >> 7, e = i & 127;
        wk_s[k * 136 + e] = to_tf32(wk[k * 128 + e]);
    }
    for (int i = tid; i < 32 * 32; i += 256) {
        int k = i >> 5, c = i & 31;
        wv_s[k * 44 + c] = to_tf32(wv[k * 32 + c]);
    }
    float itk = 1.0f / fminf(fmaxf(temp_k[h], 0.1f), 2.0f);

    float kvacc[5][4];
#pragma unroll
    for (int i = 0; i < 5; i++)
#pragma unroll
        for (int j = 0; j < 4; j++) kvacc[i][j] = 0.f;

    int row0 = blockIdx.x * 1024;

    for (int ch = 0; ch < 16; ch++) {
        __syncthreads();
        {
            int r = tid >> 2, c0 = (tid & 3) * 8;
            const float* src = xm + (size_t)(row0 + ch * 64 + r) * DMODEL + h * DHEAD + c0;
            float4 v1 = *(const float4*)src, v2 = *(const float4*)(src + 4);
            float* dst = &xm_s[r * 36 + c0];
            dst[0] = to_tf32(v1.x); dst[1] = to_tf32(v1.y);
            dst[2] = to_tf32(v1.z); dst[3] = to_tf32(v1.w);
            dst[4] = to_tf32(v2.x); dst[5] = to_tf32(v2.y);
            dst[6] = to_tf32(v2.z); dst[7] = to_tf32(v2.w);
        }
        __syncthreads();

        {
            int wm = (wid & 3) * 16, wn = (wid >> 2) * 64;
            float acc[8][4];
#pragma unroll
            for (int i = 0; i < 8; i++)
#pragma unroll
                for (int j = 0; j < 4; j++) acc[i][j] = 0.f;
#pragma unroll
            for (int ks = 0; ks < 32; ks += 8) {
                uint32_t a[4];
                a[0] = __float_as_uint(xm_s[(wm + lr) * 36 + ks + lc]);
                a[1] = __float_as_uint(xm_s[(wm + lr + 8) * 36 + ks + lc]);
                a[2] = __float_as_uint(xm_s[(wm + lr) * 36 + ks + lc + 4]);
                a[3] = __float_as_uint(xm_s[(wm + lr + 8) * 36 + ks + lc + 4]);
#pragma unroll
                for (int nt = 0; nt < 8; nt++) {
                    uint32_t b[2];
                    b[0] = __float_as_uint(wk_s[(ks + lc) * 136 + wn + nt * 8 + lr]);
                    b[1] = __float_as_uint(wk_s[(ks + lc + 4) * 136 + wn + nt * 8 + lr]);
                    mma_tf32(acc[nt], a, b);
                }
            }
#pragma unroll
            for (int nt = 0; nt < 8; nt++) {
                int col = wn + nt * 8 + 2 * lc;
                int r = wm + lr;
                kT_s[col * 68 + r]           = to_tf32(__expf(acc[nt][0] * itk));
                kT_s[(col + 1) * 68 + r]     = to_tf32(__expf(acc[nt][1] * itk));
                kT_s[col * 68 + r + 8]       = to_tf32(__expf(acc[nt][2] * itk));
                kT_s[(col + 1) * 68 + r + 8] = to_tf32(__expf(acc[nt][3] * itk));
            }
        }
        if (wid < 4) {
            int wm = wid * 16;
            float acc[4][4];
#pragma unroll
            for (int i = 0; i < 4; i++)
#pragma unroll
                for (int j = 0; j < 4; j++) acc[i][j] = 0.f;
#pragma unroll
            for (int ks = 0; ks < 32; ks += 8) {
                uint32_t a[4];
                a[0] = __float_as_uint(xm_s[(wm + lr) * 36 + ks + lc]);
                a[1] = __float_as_uint(xm_s[(wm + lr + 8) * 36 + ks + lc]);
                a[2] = __float_as_uint(xm_s[(wm + lr) * 36 + ks + lc + 4]);
                a[3] = __float_as_uint(xm_s[(wm + lr + 8) * 36 + ks + lc + 4]);
#pragma unroll
                for (int nt = 0; nt < 4; nt++) {
                    uint32_t b[2];
                    b[0] = __float_as_uint(wv_s[(ks + lc) * 44 + nt * 8 + lr]);
                    b[1] = __float_as_uint(wv_s[(ks + lc + 4) * 44 + nt * 8 + lr]);
                    mma_tf32(acc[nt], a, b);
                }
            }
#pragma unroll
            for (int nt = 0; nt < 4; nt++) {
                int col = nt * 8 + 2 * lc;
                int r = wm + lr;
                v_s[r * 44 + col]           = to_tf32(acc[nt][0]);
                v_s[r * 44 + col + 1]       = to_tf32(acc[nt][1]);
                v_s[(r + 8) * 44 + col]     = to_tf32(acc[nt][2]);
                v_s[(r + 8) * 44 + col + 1] = to_tf32(acc[nt][3]);
            }
        }
        if (tid < 64) v_s[tid * 44 + 32] = 1.0f;
        __syncthreads();

        {
            int we = wid * 16;
#pragma unroll
            for (int ks = 0; ks < 64; ks += 8) {
                uint32_t a[4];
                a[0] = __float_as_uint(kT_s[(we + lr) * 68 + ks + lc]);
                a[1] = __float_as_uint(kT_s[(we + lr + 8) * 68 + ks + lc]);
                a[2] = __float_as_uint(kT_s[(we + lr) * 68 + ks + lc + 4]);
                a[3] = __float_as_uint(kT_s[(we + lr + 8) * 68 + ks + lc + 4]);
#pragma unroll
                for (int nt = 0; nt < 5; nt++) {
                    uint32_t b[2];
                    b[0] = __float_as_uint(v_s[(ks + lc) * 44 + nt * 8 + lr]);
                    b[1] = __float_as_uint(v_s[(ks + lc + 4) * 44 + nt * 8 + lr]);
                    mma_tf32(kvacc[nt], a, b);
                }
            }
        }
    }
    {
        int we = wid * 16;
#pragma unroll
        for (int nt = 0; nt < 5; nt++) {
            int col = nt * 8 + 2 * lc;
            int e0 = we + lr, e1 = we + lr + 8;
            if (col <= 32) {
                atomicAdd(&kvout[(h * QKDIM + e0) * 40 + col], kvacc[nt][0]);
                atomicAdd(&kvout[(h * QKDIM + e1) * 40 + col], kvacc[nt][2]);
            }
            if (col + 1 <= 32) {
                atomicAdd(&kvout[(h * QKDIM + e0) * 40 + col + 1], kvacc[nt][1]);
                atomicAdd(&kvout[(h * QKDIM + e1) * 40 + col + 1], kvacc[nt][3]);
            }
        }
    }
}

// ================= tensor-core QKV =================
#define QKV_SMEM_FLOATS (128*36*2 + 32*136 + 64*36 + 64*132)
__global__ void qkv_mma_kernel(const float* __restrict__ xm, const float* __restrict__ wq,
                               const float* __restrict__ temp_q, const float* __restrict__ kv2,
                               float* __restrict__ out) {
    extern __shared__ float sm[];
    float* kvh  = sm;                    // [128][36]
    float* kvl  = kvh + 128 * 36;        // [128][36]
    float* wq_s = kvl + 128 * 36;        // [32][136]
    float* xm_s = wq_s + 32 * 136;       // [64][36]
    float* q_s  = xm_s + 64 * 36;        // [64][132]

    int h = blockIdx.y;
    int row0 = blockIdx.x * 64;
    int tid = threadIdx.x;
    int wid = tid >> 5, lane = tid & 31;
    int lr = lane >> 2, lc = lane & 3;

    for (int i = tid; i < 32 * 128; i += 256) {
        int k = i >> 7, e = i & 127;
        wq_s[k * 136 + e] = to_tf32(wq[k * 128 + e]);
    }
    for (int i = tid; i < 128 * 32; i += 256) {
        int e = i >> 5, c = i & 31;
        float kvv = kv2[(h * QKDIM + e) * 40 + c] / kv2[(h * QKDIM + e) * 40 + 32];
        float hi = to_tf32(kvv);
        kvh[e * 36 + c] = hi;
        kvl[e * 36 + c] = to_tf32(kvv - hi);
    }
    {
        int r = tid >> 2, c0 = (tid & 3) * 8;
        const float* src = xm + (size_t)(row0 + r) * DMODEL + h * DHEAD + c0;
        float4 v1 = *(const float4*)src, v2 = *(const float4*)(src + 4);
        float* dst = &xm_s[r * 36 + c0];
        dst[0] = to_tf32(v1.x); dst[1] = to_tf32(v1.y);
        dst[2] = to_tf32(v1.z); dst[3] = to_tf32(v1.w);
        dst[4] = to_tf32(v2.x); dst[5] = to_tf32(v2.y);
        dst[6] = to_tf32(v2.z); dst[7] = to_tf32(v2.w);
    }
    float itq = 1.0f / fminf(fmaxf(temp_q[h], 0.1f), 2.0f);
    __syncthreads();

    {
        int wm = (wid & 3) * 16, wn = (wid >> 2) * 64;
        float acc[8][4];
#pragma unroll
        for (int i = 0; i < 8; i++)
#pragma unroll
            for (int j = 0; j < 4; j++) acc[i][j] = 0.f;
#pragma unroll
        for (int ks = 0; ks < 32; ks += 8) {
            uint32_t a[4];
            a[0] = __float_as_uint(xm_s[(wm + lr) * 36 + ks + lc]);
            a[1] = __float_as_uint(xm_s[(wm + lr + 8) * 36 + ks + lc]);
            a[2] = __float_as_uint(xm_s[(wm + lr) * 36 + ks + lc + 4]);
            a[3] = __float_as_uint(xm_s[(wm + lr + 8) * 36 + ks + lc + 4]);
#pragma unroll
            for (int nt = 0; nt < 8; nt++) {
                uint32_t b[2];
                b[0] = __float_as_uint(wq_s[(ks + lc) * 136 + wn + nt * 8 + lr]);
                b[1] = __float_as_uint(wq_s[(ks + lc + 4) * 136 + wn + nt * 8 + lr]);
                mma_tf32(acc[nt], a, b);
            }
        }
#pragma unroll
        for (int nt = 0; nt < 8; nt++) {
            int col = wn + nt * 8 + 2 * lc;
            int r = wm + lr;
            q_s[r * 132 + col]           = acc[nt][0] * itq;
            q_s[r * 132 + col + 1]       = acc[nt][1] * itq;
            q_s[(r + 8) * 132 + col]     = acc[nt][2] * itq;
            q_s[(r + 8) * 132 + col + 1] = acc[nt][3] * itq;
        }
    }
    __syncthreads();
    {
        int r = tid >> 2, sub = tid & 3;
        float* row = q_s + r * 132;
        float mx = -1e30f;
#pragma unroll
        for (int k = 0; k < 32; k++) mx = fmaxf(mx, row[sub + k * 4]);
        mx = fmaxf(mx, __shfl_xor_sync(0xffffffffu, mx, 1));
        mx = fmaxf(mx, __shfl_xor_sync(0xffffffffu, mx, 2));
        float ev[32], sum = 0.f;
#pragma unroll
        for (int k = 0; k < 32; k++) { ev[k] = __expf(row[sub + k * 4] - mx); sum += ev[k]; }
        sum += __shfl_xor_sync(0xffffffffu, sum, 1);
        sum += __shfl_xor_sync(0xffffffffu, sum, 2);
        float inv = 1.0f / sum;
#pragma unroll
        for (int k = 0; k < 32; k++) row[sub + k * 4] = to_tf32(ev[k] * inv);
    }
    __syncthreads();
    {
        int wm = (wid & 3) * 16;
        int part = wid >> 2;
        const float* kvp = part ? kvl : kvh;
        float acc[4][4];
#pragma unroll
        for (int i = 0; i < 4; i++)
#pragma unroll
            for (int j = 0; j < 4; j++) acc[i][j] = 0.f;
#pragma unroll
        for (int ks = 0; ks < 128; ks += 8) {
            uint32_t a[4];
            a[0] = __float_as_uint(q_s[(wm + lr) * 132 + ks + lc]);
            a[1] = __float_as_uint(q_s[(wm + lr + 8) * 132 + ks + lc]);
            a[2] = __float_as_uint(q_s[(wm + lr) * 132 + ks + lc + 4]);
            a[3] = __float_as_uint(q_s[(wm + lr + 8) * 132 + ks + lc + 4]);
#pragma unroll
            for (int nt = 0; nt < 4; nt++) {
                uint32_t b[2];
                b[0] = __float_as_uint(kvp[(ks + lc) * 36 + nt * 8 + lr]);
                b[1] = __float_as_uint(kvp[(ks + lc + 4) * 36 + nt * 8 + lr]);
                mma_tf32(acc[nt], a, b);
            }
        }
        if (part == 1) {
#pragma unroll
            for (int nt = 0; nt < 4; nt++) {
                int col = nt * 8 + 2 * lc;
                int r = wm + lr;
                xm_s[r * 36 + col]           = acc[nt][0];
                xm_s[r * 36 + col + 1]       = acc[nt][1];
                xm_s[(r + 8) * 36 + col]     = acc[nt][2];
                xm_s[(r + 8) * 36 + col + 1] = acc[nt][3];
            }
        }
        __syncthreads();
        if (part == 0) {
#pragma unroll
            for (int nt = 0; nt < 4; nt++) {
                int col = nt * 8 + 2 * lc;
#pragma unroll
                for (int half = 0; half < 2; half++) {
                    int r = wm + lr + half * 8;
                    float v0 = acc[nt][half * 2 + 0] + xm_s[r * 36 + col];
                    float v1 = acc[nt][half * 2 + 1] + xm_s[r * 36 + col + 1];
                    float2 o; o.x = v0; o.y = v1;
                    *(float2*)(out + (size_t)(row0 + r) * DMODEL + h * DHEAD + col) = o;
                }
            }
        }
    }
}

// ---------------- head: out[n] = LN(fx) @ head_w + head_b ----------------
__global__ void head_kernel(const float* __restrict__ fx, const float* __restrict__ g,
                            const float* __restrict__ b, const float* __restrict__ hw,
                            const float* __restrict__ hb, float* __restrict__ out) {
    __shared__ float sh[8];
    int n = blockIdx.x, t = threadIdx.x;
    float v = fx[(size_t)n * DMODEL + t];
    float mean = block_sum256(v, sh) * (1.0f / DMODEL);
    float d = v - mean;
    float var = block_sum256(d * d, sh) * (1.0f / DMODEL);
    float rstd = rsqrtf(var + 1e-5f);
    float hn = d * rstd * g[t] + b[t];
    float dot = block_sum256(hn * hw[t], sh);
    if (t == 0) out[n] = dot + hb[0];
}

// ---------------- launch ----------------
extern "C" void kernel_launch(void* const* d_in, const int* in_sizes, int n_in,
                              void* d_out, int out_size) {
    const float* x          = (const float*)d_in[0];
    const float* pre_w1     = (const float*)d_in[1];
    const float* pre_b1     = (const float*)d_in[2];
    const float* pre_w2     = (const float*)d_in[3];
    const float* pre_b2     = (const float*)d_in[4];
    const float* placeholder= (const float*)d_in[5];
    const float* ln1_g      = (const float*)d_in[6];
    const float* ln1_b      = (const float*)d_in[7];
    const float* inp_w      = (const float*)d_in[8];
    const float* inp_b      = (const float*)d_in[9];
    const float* temp_q     = (const float*)d_in[10];
    const float* temp_k     = (const float*)d_in[11];
    const float* wq         = (const float*)d_in[12];
    const float* wk         = (const float*)d_in[13];
    const float* wv         = (const float*)d_in[14];
    const float* out_w1     = (const float*)d_in[15];
    const float* out_b1     = (const float*)d_in[16];
    const float* out_w2     = (const float*)d_in[17];
    const float* out_b2     = (const float*)d_in[18];
    const float* ln2_g      = (const float*)d_in[19];
    const float* ln2_b      = (const float*)d_in[20];
    const float* mlp_w1     = (const float*)d_in[21];
    const float* mlp_b1     = (const float*)d_in[22];
    const float* mlp_w2     = (const float*)d_in[23];
    const float* mlp_b2     = (const float*)d_in[24];
    const float* ln3_g      = (const float*)d_in[25];
    const float* ln3_b      = (const float*)d_in[26];
    const float* head_w     = (const float*)d_in[27];
    const float* head_b     = (const float*)d_in[28];

    float *fx, *t1, *t2, *t3, *hidden, *kv2;
    cudaGetSymbolAddress((void**)&fx, g_fx);
    cudaGetSymbolAddress((void**)&t1, g_t1);
    cudaGetSymbolAddress((void**)&t2, g_t2);
    cudaGetSymbolAddress((void**)&t3, g_t3);
    cudaGetSymbolAddress((void**)&hidden, g_hidden);
    cudaGetSymbolAddress((void**)&kv2, g_kv2);

    const int gemm_smem = GEMM_SMEM_FLOATS * 4;
    const int kv_smem = KV_SMEM_FLOATS * 4;
    const int qkv_smem = QKV_SMEM_FLOATS * 4;
    cudaFuncSetAttribute(gemm_kernel, cudaFuncAttributeMaxDynamicSharedMemorySize, gemm_smem);
    cudaFuncSetAttribute(kv_mma_kernel, cudaFuncAttributeMaxDynamicSharedMemorySize, kv_smem);
    cudaFuncSetAttribute(qkv_mma_kernel, cudaFuncAttributeMaxDynamicSharedMemorySize, qkv_smem);

    dim3 ggrid(NPTS / TBM, DMODEL / TBN);

    pre1_kernel<<<NPTS * 512 / 256, 256>>>(x, pre_w1, pre_b1, hidden);
    gemm_kernel<<<ggrid, 256, gemm_smem>>>(hidden, 512, pre_w2, pre_b2, placeholder, nullptr, fx, 0);

    for (int i = 0; i < NLAYERS; i++) {
        const float* iw  = inp_w + (size_t)i * 65536;
        const float* ow1 = out_w1 + (size_t)i * 65536;
        const float* ow2 = out_w2 + (size_t)i * 65536;
        const float* mw1 = mlp_w1 + (size_t)i * 65536;
        const float* mw2 = mlp_w2 + (size_t)i * 65536;

        ln_kernel<<<NPTS / 8, 256>>>(fx, ln1_g + i * 256, ln1_b + i * 256, t1);
        gemm_kernel<<<ggrid, 256, gemm_smem>>>(t1, 256, iw, inp_b + i * 256, nullptr, nullptr, t2, 0);
        zero_kv_kernel<<<(NH * QKDIM * 40 + 255) / 256, 256>>>();
        kv_mma_kernel<<<dim3(32, NH), 256, kv_smem>>>(t2, wk + (size_t)i * 4096,
                                                      wv + (size_t)i * 1024, temp_k + i * NH, kv2);
        qkv_mma_kernel<<<dim3(NPTS / 64, NH), 256, qkv_smem>>>(t2, wq + (size_t)i * 4096,
                                                               temp_q + i * NH, kv2, t3);
        gemm_kernel<<<ggrid, 256, gemm_smem>>>(t3, 256, ow1, out_b1 + i * 256, nullptr, nullptr, t1, 1);
        gemm_kernel<<<ggrid, 256, gemm_smem>>>(t1, 256, ow2, out_b2 + i * 256, nullptr, fx, fx, 0);
        ln_kernel<<<NPTS / 8, 256>>>(fx, ln2_g + i * 256, ln2_b + i * 256, t1);
        gemm_kernel<<<ggrid, 256, gemm_smem>>>(t1, 256, mw1, mlp_b1 + i * 256, nullptr, nullptr, t2, 1);
        gemm_kernel<<<ggrid, 256, gemm_smem>>>(t2, 256, mw2, mlp_b2 + i * 256, nullptr, fx, fx, 0);
    }
    head_kernel<<<NPTS, 256>>>(fx, ln3_g, ln3_b, head_w, head_b, (float*)d_out);
}

// round 5
// speedup vs baseline: 2.8911x; 1.0480x over previous
#include <cuda_runtime.h>
#include <math.h>
#include <stdint.h>

#define NPTS 32768
#define DMODEL 256
#define NH 8
#define DHEAD 32
#define QKDIM 128
#define NLAYERS 5

// ---------------- static device scratch (no allocs allowed) ----------------
__device__ float g_fx[NPTS * DMODEL];
__device__ float g_t1[NPTS * DMODEL];
__device__ float g_t2[NPTS * DMODEL];
__device__ float g_t3[NPTS * DMODEL];
__device__ float g_hidden[NPTS * 512];
__device__ float g_kv2[NH * QKDIM * 40];   // [h][e][c], c=32 holds S
// converted (tf32-rounded) weights: [inp|ow1|ow2|mw1|mw2] (5*327680) + pre_w2 (131072)
#define WCONV_PER 327680
__device__ float g_wc[5 * WCONV_PER + 131072];

__device__ __forceinline__ float gelu_f(float x) {
    return 0.5f * x * (1.0f + erff(x * 0.70710678118654752f));
}

__device__ __forceinline__ float to_tf32(float x) {
    uint32_t u;
    asm("cvt.rna.tf32.f32 %0, %1;" : "=r"(u) : "f"(x));
    return __uint_as_float(u);
}

__device__ __forceinline__ void mma_tf32(float* c, const uint32_t* a, const uint32_t* b) {
    asm volatile(
        "mma.sync.aligned.m16n8k8.row.col.f32.tf32.tf32.f32 "
        "{%0,%1,%2,%3}, {%4,%5,%6,%7}, {%8,%9}, {%0,%1,%2,%3};\n"
        : "+f"(c[0]), "+f"(c[1]), "+f"(c[2]), "+f"(c[3])
        : "r"(a[0]), "r"(a[1]), "r"(a[2]), "r"(a[3]), "r"(b[0]), "r"(b[1]));
}

__device__ __forceinline__ void cpa16(float* dst, const float* src) {
    uint32_t d = (uint32_t)__cvta_generic_to_shared(dst);
    asm volatile("cp.async.cg.shared.global [%0], [%1], 16;\n" :: "r"(d), "l"(src));
}

// block-wide sum for 256 threads; result broadcast to all threads
__device__ __forceinline__ float block_sum256(float v, volatile float* sh) {
    int lane = threadIdx.x & 31;
#pragma unroll
    for (int o = 16; o > 0; o >>= 1) v += __shfl_down_sync(0xffffffffu, v, o);
    if (lane == 0) sh[threadIdx.x >> 5] = v;
    __syncthreads();
    if (threadIdx.x < 32) {
        float r = (lane < 8) ? sh[lane] : 0.f;
#pragma unroll
        for (int o = 4; o > 0; o >>= 1) r += __shfl_down_sync(0xffffffffu, r, o);
        if (lane == 0) sh[0] = r;
    }
    __syncthreads();
    float out = sh[0];
    __syncthreads();
    return out;
}

// ---------------- tf32 weight conversion ----------------
__global__ void conv_tf32_kernel(const float* __restrict__ src, float* __restrict__ dst, int n4) {
    int i = blockIdx.x * 256 + threadIdx.x;
    if (i < n4) {
        float4 v = ((const float4*)src)[i];
        v.x = to_tf32(v.x); v.y = to_tf32(v.y);
        v.z = to_tf32(v.z); v.w = to_tf32(v.w);
        ((float4*)dst)[i] = v;
    }
}

// ---------------- preprocess: hidden = tf32(gelu(x @ pre_w1 + b1)) ----------------
__global__ void pre1_kernel(const float* __restrict__ x, const float* __restrict__ w1,
                            const float* __restrict__ b1, float* __restrict__ hidden) {
    int idx = blockIdx.x * 256 + threadIdx.x;
    int n = idx >> 9, j = idx & 511;
    float x0 = x[n * 3 + 0], x1 = x[n * 3 + 1], x2 = x[n * 3 + 2];
    float a = x0 * w1[j] + x1 * w1[512 + j] + x2 * w1[1024 + j] + b1[j];
    hidden[idx] = to_tf32(gelu_f(a));
}

// ---------------- tf32 tensor-core GEMM, cp.async double-buffered ----------------
// inputs A, W are PRE-ROUNDED tf32 values stored as f32.
#define TBM 128
#define TBN 128
#define TBK 32
#define AS_STRIDE 36
#define BS_STRIDE 136
#define AS_FLOATS (TBM * AS_STRIDE)
#define BS_FLOATS (TBK * BS_STRIDE)
#define GEMM_SMEM_FLOATS (2 * (AS_FLOATS + BS_FLOATS))
__global__ __launch_bounds__(256, 2)
void gemm_kernel(const float* __restrict__ A, int K,
                 const float* __restrict__ W,
                 const float* __restrict__ bias,
                 const float* __restrict__ colbias,
                 const float* __restrict__ residual,
                 float* __restrict__ Y, int act, int rnd) {
    extern __shared__ float smem[];
    float* As = smem;
    float* Bs = smem + 2 * AS_FLOATS;

    int m0 = blockIdx.x * TBM;
    int n0 = blockIdx.y * TBN;
    int tid = threadIdx.x;
    int wid = tid >> 5, lane = tid & 31;
    int wm = (wid >> 2) * 64;
    int wn = (wid & 3) * 32;
    int lr = lane >> 2;
    int lc = lane & 3;

    float acc[4][4][4];
#pragma unroll
    for (int i = 0; i < 4; i++)
#pragma unroll
        for (int j = 0; j < 4; j++)
#pragma unroll
            for (int k = 0; k < 4; k++) acc[i][j][k] = 0.f;

    int a_r = tid >> 3;
    int a_kc = (tid & 7) * 4;
    int b_kr = tid >> 5;
    int b_nc = lane * 4;

    int nit = K / TBK;

    {
        float* as = As;
        float* bs = Bs;
#pragma unroll
        for (int rr = 0; rr < 4; rr++) {
            int row = a_r + rr * 32;
            cpa16(&as[row * AS_STRIDE + a_kc], A + (size_t)(m0 + row) * K + a_kc);
        }
#pragma unroll
        for (int kk = 0; kk < 4; kk++) {
            int krow = b_kr + kk * 8;
            cpa16(&bs[krow * BS_STRIDE + b_nc], W + (size_t)krow * DMODEL + n0 + b_nc);
        }
        asm volatile("cp.async.commit_group;\n");
    }

    for (int it = 0; it < nit; it++) {
        int cur = it & 1;
        if (it + 1 < nit) {
            int nxt = (it + 1) & 1;
            int k0 = (it + 1) * TBK;
            float* as = As + nxt * AS_FLOATS;
            float* bs = Bs + nxt * BS_FLOATS;
#pragma unroll
            for (int rr = 0; rr < 4; rr++) {
                int row = a_r + rr * 32;
                cpa16(&as[row * AS_STRIDE + a_kc], A + (size_t)(m0 + row) * K + k0 + a_kc);
            }
#pragma unroll
            for (int kk = 0; kk < 4; kk++) {
                int krow = b_kr + kk * 8;
                cpa16(&bs[krow * BS_STRIDE + b_nc], W + (size_t)(k0 + krow) * DMODEL + n0 + b_nc);
            }
            asm volatile("cp.async.commit_group;\n");
            asm volatile("cp.async.wait_group 1;\n");
        } else {
            asm volatile("cp.async.wait_group 0;\n");
        }
        __syncthreads();

        const float* as = As + cur * AS_FLOATS;
        const float* bs = Bs + cur * BS_FLOATS;
#pragma unroll
        for (int ks = 0; ks < TBK; ks += 8) {
            uint32_t af[4][4], bf[4][2];
#pragma unroll
            for (int mt = 0; mt < 4; mt++) {
                int r = wm + mt * 16 + lr;
                int c = ks + lc;
                af[mt][0] = __float_as_uint(as[r * AS_STRIDE + c]);
                af[mt][1] = __float_as_uint(as[(r + 8) * AS_STRIDE + c]);
                af[mt][2] = __float_as_uint(as[r * AS_STRIDE + c + 4]);
                af[mt][3] = __float_as_uint(as[(r + 8) * AS_STRIDE + c + 4]);
            }
#pragma unroll
            for (int nt = 0; nt < 4; nt++) {
                int n = wn + nt * 8 + lr;
                int c = ks + lc;
                bf[nt][0] = __float_as_uint(bs[c * BS_STRIDE + n]);
                bf[nt][1] = __float_as_uint(bs[(c + 4) * BS_STRIDE + n]);
            }
#pragma unroll
            for (int mt = 0; mt < 4; mt++)
#pragma unroll
                for (int nt = 0; nt < 4; nt++)
                    mma_tf32(acc[mt][nt], af[mt], bf[nt]);
        }
        __syncthreads();
    }

#pragma unroll
    for (int mt = 0; mt < 4; mt++) {
        int row = m0 + wm + mt * 16 + lr;
#pragma unroll
        for (int nt = 0; nt < 4; nt++) {
            int col = n0 + wn + nt * 8 + lc * 2;
#pragma unroll
            for (int half = 0; half < 2; half++) {
                int r = row + half * 8;
                float v0 = acc[mt][nt][half * 2 + 0];
                float v1 = acc[mt][nt][half * 2 + 1];
                if (bias)    { v0 += bias[col];        v1 += bias[col + 1]; }
                if (colbias) { v0 += colbias[col];     v1 += colbias[col + 1]; }
                if (act)     { v0 = gelu_f(v0);        v1 = gelu_f(v1); }
                if (residual) {
                    v0 += residual[(size_t)r * DMODEL + col];
                    v1 += residual[(size_t)r * DMODEL + col + 1];
                }
                if (rnd)     { v0 = to_tf32(v0);       v1 = to_tf32(v1); }
                float2 o; o.x = v0; o.y = v1;
                *(float2*)(Y + (size_t)r * DMODEL + col) = o;
            }
        }
    }
}

// ---------------- LayerNorm: warp per row, single pass, tf32-rounded output ----------------
__global__ void ln_kernel(const float* __restrict__ X, const float* __restrict__ g,
                          const float* __restrict__ b, float* __restrict__ Y) {
    int wid = threadIdx.x >> 5, lane = threadIdx.x & 31;
    int row = blockIdx.x * 8 + wid;
    const float4* X4 = (const float4*)(X + (size_t)row * DMODEL);
    const float4* G4 = (const float4*)g;
    const float4* B4 = (const float4*)b;
    float4* Y4 = (float4*)(Y + (size_t)row * DMODEL);

    float4 a = X4[lane];
    float4 c = X4[lane + 32];
    float s = a.x + a.y + a.z + a.w + c.x + c.y + c.z + c.w;
    float q = a.x * a.x + a.y * a.y + a.z * a.z + a.w * a.w
            + c.x * c.x + c.y * c.y + c.z * c.z + c.w * c.w;
#pragma unroll
    for (int o = 16; o > 0; o >>= 1) {
        s += __shfl_xor_sync(0xffffffffu, s, o);
        q += __shfl_xor_sync(0xffffffffu, q, o);
    }
    float mean = s * (1.0f / DMODEL);
    float var = q * (1.0f / DMODEL) - mean * mean;
    float rstd = rsqrtf(fmaxf(var, 0.f) + 1e-5f);

    float4 g1 = G4[lane], g2 = G4[lane + 32];
    float4 b1 = B4[lane], b2 = B4[lane + 32];
    float4 o1, o2;
    o1.x = to_tf32((a.x - mean) * rstd * g1.x + b1.x);
    o1.y = to_tf32((a.y - mean) * rstd * g1.y + b1.y);
    o1.z = to_tf32((a.z - mean) * rstd * g1.z + b1.z);
    o1.w = to_tf32((a.w - mean) * rstd * g1.w + b1.w);
    o2.x = to_tf32((c.x - mean) * rstd * g2.x + b2.x);
    o2.y = to_tf32((c.y - mean) * rstd * g2.y + b2.y);
    o2.z = to_tf32((c.z - mean) * rstd * g2.z + b2.z);
    o2.w = to_tf32((c.w - mean) * rstd * g2.w + b2.w);
    Y4[lane] = o1;
    Y4[lane + 32] = o2;
}

// ---------------- zero kv accumulators ----------------
__global__ void zero_kv_kernel() {
    int idx = blockIdx.x * 256 + threadIdx.x;
    if (idx < NH * QKDIM * 40) g_kv2[idx] = 0.f;
}

// ================= tensor-core KV =================
#define KV_SMEM_FLOATS (32*136 + 32*44 + 64*36 + 128*68 + 64*44)
__global__ void kv_mma_kernel(const float* __restrict__ xm, const float* __restrict__ wk,
                              const float* __restrict__ wv, const float* __restrict__ temp_k,
                              float* __restrict__ kvout) {
    extern __shared__ float sm[];
    float* wk_s = sm;
    float* wv_s = wk_s + 32 * 136;
    float* xm_s = wv_s + 32 * 44;
    float* kT_s = xm_s + 64 * 36;
    float* v_s  = kT_s + 128 * 68;

    int h = blockIdx.y;
    int tid = threadIdx.x;
    int wid = tid >> 5, lane = tid & 31;
    int lr = lane >> 2, lc = lane & 3;

    for (int i = tid; i < 32 * 128; i += 256) {
        int k = i >> 7, e = i & 127;
        wk_s[k * 136 + e] = to_tf32(wk[k * 128 + e]);
    }
    for (int i = tid; i < 32 * 32; i += 256) {
        int k = i >> 5, c = i & 31;
        wv_s[k * 44 + c] = to_tf32(wv[k * 32 + c]);
    }
    float itk = 1.0f / fminf(fmaxf(temp_k[h], 0.1f), 2.0f);

    float kvacc[5][4];
#pragma unroll
    for (int i = 0; i < 5; i++)
#pragma unroll
        for (int j = 0; j < 4; j++) kvacc[i][j] = 0.f;

    int row0 = blockIdx.x * 1024;

    for (int ch = 0; ch < 16; ch++) {
        __syncthreads();
        {
            int r = tid >> 2, c0 = (tid & 3) * 8;
            const float* src = xm + (size_t)(row0 + ch * 64 + r) * DMODEL + h * DHEAD + c0;
            float4 v1 = *(const float4*)src, v2 = *(const float4*)(src + 4);
            float* dst = &xm_s[r * 36 + c0];
            dst[0] = v1.x; dst[1] = v1.y; dst[2] = v1.z; dst[3] = v1.w;
            dst[4] = v2.x; dst[5] = v2.y; dst[6] = v2.z; dst[7] = v2.w;
        }
        __syncthreads();

        {
            int wm = (wid & 3) * 16, wn = (wid >> 2) * 64;
            float acc[8][4];
#pragma unroll
            for (int i = 0; i < 8; i++)
#pragma unroll
                for (int j = 0; j < 4; j++) acc[i][j] = 0.f;
#pragma unroll
            for (int ks = 0; ks < 32; ks += 8) {
                uint32_t a[4];
                a[0] = __float_as_uint(xm_s[(wm + lr) * 36 + ks + lc]);
                a[1] = __float_as_uint(xm_s[(wm + lr + 8) * 36 + ks + lc]);
                a[2] = __float_as_uint(xm_s[(wm + lr) * 36 + ks + lc + 4]);
                a[3] = __float_as_uint(xm_s[(wm + lr + 8) * 36 + ks + lc + 4]);
#pragma unroll
                for (int nt = 0; nt < 8; nt++) {
                    uint32_t b[2];
                    b[0] = __float_as_uint(wk_s[(ks + lc) * 136 + wn + nt * 8 + lr]);
                    b[1] = __float_as_uint(wk_s[(ks + lc + 4) * 136 + wn + nt * 8 + lr]);
                    mma_tf32(acc[nt], a, b);
                }
            }
#pragma unroll
            for (int nt = 0; nt < 8; nt++) {
                int col = wn + nt * 8 + 2 * lc;
                int r = wm + lr;
                kT_s[col * 68 + r]           = to_tf32(__expf(acc[nt][0] * itk));
                kT_s[(col + 1) * 68 + r]     = to_tf32(__expf(acc[nt][1] * itk));
                kT_s[col * 68 + r + 8]       = to_tf32(__expf(acc[nt][2] * itk));
                kT_s[(col + 1) * 68 + r + 8] = to_tf32(__expf(acc[nt][3] * itk));
            }
        }
        if (wid < 4) {
            int wm = wid * 16;
            float acc[4][4];
#pragma unroll
            for (int i = 0; i < 4; i++)
#pragma unroll
                for (int j = 0; j < 4; j++) acc[i][j] = 0.f;
#pragma unroll
            for (int ks = 0; ks < 32; ks += 8) {
                uint32_t a[4];
                a[0] = __float_as_uint(xm_s[(wm + lr) * 36 + ks + lc]);
                a[1] = __float_as_uint(xm_s[(wm + lr + 8) * 36 + ks + lc]);
                a[2] = __float_as_uint(xm_s[(wm + lr) * 36 + ks + lc + 4]);
                a[3] = __float_as_uint(xm_s[(wm + lr + 8) * 36 + ks + lc + 4]);
#pragma unroll
                for (int nt = 0; nt < 4; nt++) {
                    uint32_t b[2];
                    b[0] = __float_as_uint(wv_s[(ks + lc) * 44 + nt * 8 + lr]);
                    b[1] = __float_as_uint(wv_s[(ks + lc + 4) * 44 + nt * 8 + lr]);
                    mma_tf32(acc[nt], a, b);
                }
            }
#pragma unroll
            for (int nt = 0; nt < 4; nt++) {
                int col = nt * 8 + 2 * lc;
                int r = wm + lr;
                v_s[r * 44 + col]           = to_tf32(acc[nt][0]);
                v_s[r * 44 + col + 1]       = to_tf32(acc[nt][1]);
                v_s[(r + 8) * 44 + col]     = to_tf32(acc[nt][2]);
                v_s[(r + 8) * 44 + col + 1] = to_tf32(acc[nt][3]);
            }
        }
        if (tid < 64) v_s[tid * 44 + 32] = 1.0f;
        __syncthreads();

        {
            int we = wid * 16;
#pragma unroll
            for (int ks = 0; ks < 64; ks += 8) {
                uint32_t a[4];
                a[0] = __float_as_uint(kT_s[(we + lr) * 68 + ks + lc]);
                a[1] = __float_as_uint(kT_s[(we + lr + 8) * 68 + ks + lc]);
                a[2] = __float_as_uint(kT_s[(we + lr) * 68 + ks + lc + 4]);
                a[3] = __float_as_uint(kT_s[(we + lr + 8) * 68 + ks + lc + 4]);
#pragma unroll
                for (int nt = 0; nt < 5; nt++) {
                    uint32_t b[2];
                    b[0] = __float_as_uint(v_s[(ks + lc) * 44 + nt * 8 + lr]);
                    b[1] = __float_as_uint(v_s[(ks + lc + 4) * 44 + nt * 8 + lr]);
                    mma_tf32(kvacc[nt], a, b);
                }
            }
        }
    }
    {
        int we = wid * 16;
#pragma unroll
        for (int nt = 0; nt < 5; nt++) {
            int col = nt * 8 + 2 * lc;
            int e0 = we + lr, e1 = we + lr + 8;
            if (col <= 32) {
                atomicAdd(&kvout[(h * QKDIM + e0) * 40 + col], kvacc[nt][0]);
                atomicAdd(&kvout[(h * QKDIM + e1) * 40 + col], kvacc[nt][2]);
            }
            if (col + 1 <= 32) {
                atomicAdd(&kvout[(h * QKDIM + e0) * 40 + col + 1], kvacc[nt][1]);
                atomicAdd(&kvout[(h * QKDIM + e1) * 40 + col + 1], kvacc[nt][3]);
            }
        }
    }
}

// ================= tensor-core QKV =================
#define QKV_SMEM_FLOATS (128*36*2 + 32*136 + 64*36 + 64*132)
__global__ void qkv_mma_kernel(const float* __restrict__ xm, const float* __restrict__ wq,
                               const float* __restrict__ temp_q, const float* __restrict__ kv2,
                               float* __restrict__ out) {
    extern __shared__ float sm[];
    float* kvh  = sm;
    float* kvl  = kvh + 128 * 36;
    float* wq_s = kvl + 128 * 36;
    float* xm_s = wq_s + 32 * 136;
    float* q_s  = xm_s + 64 * 36;

    int h = blockIdx.y;
    int row0 = blockIdx.x * 64;
    int tid = threadIdx.x;
    int wid = tid >> 5, lane = tid & 31;
    int lr = lane >> 2, lc = lane & 3;

    for (int i = tid; i < 32 * 128; i += 256) {
        int k = i >> 7, e = i & 127;
        wq_s[k * 136 + e] = to_tf32(wq[k * 128 + e]);
    }
    for (int i = tid; i < 128 * 32; i += 256) {
        int e = i >> 5, c = i & 31;
        float kvv = kv2[(h * QKDIM + e) * 40 + c] / kv2[(h * QKDIM + e) * 40 + 32];
        float hi = to_tf32(kvv);
        kvh[e * 36 + c] = hi;
        kvl[e * 36 + c] = to_tf32(kvv - hi);
    }
    {
        int r = tid >> 2, c0 = (tid & 3) * 8;
        const float* src = xm + (size_t)(row0 + r) * DMODEL + h * DHEAD + c0;
        float4 v1 = *(const float4*)src, v2 = *(const float4*)(src + 4);
        float* dst = &xm_s[r * 36 + c0];
        dst[0] = v1.x; dst[1] = v1.y; dst[2] = v1.z; dst[3] = v1.w;
        dst[4] = v2.x; dst[5] = v2.y; dst[6] = v2.z; dst[7] = v2.w;
    }
    float itq = 1.0f / fminf(fmaxf(temp_q[h], 0.1f), 2.0f);
    __syncthreads();

    {
        int wm = (wid & 3) * 16, wn = (wid >> 2) * 64;
        float acc[8][4];
#pragma unroll
        for (int i = 0; i < 8; i++)
#pragma unroll
            for (int j = 0; j < 4; j++) acc[i][j] = 0.f;
#pragma unroll
        for (int ks = 0; ks < 32; ks += 8) {
            uint32_t a[4];
            a[0] = __float_as_uint(xm_s[(wm + lr) * 36 + ks + lc]);
            a[1] = __float_as_uint(xm_s[(wm + lr + 8) * 36 + ks + lc]);
            a[2] = __float_as_uint(xm_s[(wm + lr) * 36 + ks + lc + 4]);
            a[3] = __float_as_uint(xm_s[(wm + lr + 8) * 36 + ks + lc + 4]);
#pragma unroll
            for (int nt = 0; nt < 8; nt++) {
                uint32_t b[2];
                b[0] = __float_as_uint(wq_s[(ks + lc) * 136 + wn + nt * 8 + lr]);
                b[1] = __float_as_uint(wq_s[(ks + lc + 4) * 136 + wn + nt * 8 + lr]);
                mma_tf32(acc[nt], a, b);
            }
        }
#pragma unroll
        for (int nt = 0; nt < 8; nt++) {
            int col = wn + nt * 8 + 2 * lc;
            int r = wm + lr;
            q_s[r * 132 + col]           = acc[nt][0] * itq;
            q_s[r * 132 + col + 1]       = acc[nt][1] * itq;
            q_s[(r + 8) * 132 + col]     = acc[nt][2] * itq;
            q_s[(r + 8) * 132 + col + 1] = acc[nt][3] * itq;
        }
    }
    __syncthreads();
    {
        int r = tid >> 2, sub = tid & 3;
        float* row = q_s + r * 132;
        float mx = -1e30f;
#pragma unroll
        for (int k = 0; k < 32; k++) mx = fmaxf(mx, row[sub + k * 4]);
        mx = fmaxf(mx, __shfl_xor_sync(0xffffffffu, mx, 1));
        mx = fmaxf(mx, __shfl_xor_sync(0xffffffffu, mx, 2));
        float ev[32], sum = 0.f;
#pragma unroll
        for (int k = 0; k < 32; k++) { ev[k] = __expf(row[sub + k * 4] - mx); sum += ev[k]; }
        sum += __shfl_xor_sync(0xffffffffu, sum, 1);
        sum += __shfl_xor_sync(0xffffffffu, sum, 2);
        float inv = 1.0f / sum;
#pragma unroll
        for (int k = 0; k < 32; k++) row[sub + k * 4] = to_tf32(ev[k] * inv);
    }
    __syncthreads();
    {
        int wm = (wid & 3) * 16;
        int part = wid >> 2;
        const float* kvp = part ? kvl : kvh;
        float acc[4][4];
#pragma unroll
        for (int i = 0; i < 4; i++)
#pragma unroll
            for (int j = 0; j < 4; j++) acc[i][j] = 0.f;
#pragma unroll
        for (int ks = 0; ks < 128; ks += 8) {
            uint32_t a[4];
            a[0] = __float_as_uint(q_s[(wm + lr) * 132 + ks + lc]);
            a[1] = __float_as_uint(q_s[(wm + lr + 8) * 132 + ks + lc]);
            a[2] = __float_as_uint(q_s[(wm + lr) * 132 + ks + lc + 4]);
            a[3] = __float_as_uint(q_s[(wm + lr + 8) * 132 + ks + lc + 4]);
#pragma unroll
            for (int nt = 0; nt < 4; nt++) {
                uint32_t b[2];
                b[0] = __float_as_uint(kvp[(ks + lc) * 36 + nt * 8 + lr]);
                b[1] = __float_as_uint(kvp[(ks + lc + 4) * 36 + nt * 8 + lr]);
                mma_tf32(acc[nt], a, b);
            }
        }
        if (part == 1) {
#pragma unroll
            for (int nt = 0; nt < 4; nt++) {
                int col = nt * 8 + 2 * lc;
                int r = wm + lr;
                xm_s[r * 36 + col]           = acc[nt][0];
                xm_s[r * 36 + col + 1]       = acc[nt][1];
                xm_s[(r + 8) * 36 + col]     = acc[nt][2];
                xm_s[(r + 8) * 36 + col + 1] = acc[nt][3];
            }
        }
        __syncthreads();
        if (part == 0) {
#pragma unroll
            for (int nt = 0; nt < 4; nt++) {
                int col = nt * 8 + 2 * lc;
#pragma unroll
                for (int half = 0; half < 2; half++) {
                    int r = wm + lr + half * 8;
                    float v0 = to_tf32(acc[nt][half * 2 + 0] + xm_s[r * 36 + col]);
                    float v1 = to_tf32(acc[nt][half * 2 + 1] + xm_s[r * 36 + col + 1]);
                    float2 o; o.x = v0; o.y = v1;
                    *(float2*)(out + (size_t)(row0 + r) * DMODEL + h * DHEAD + col) = o;
                }
            }
        }
    }
}

// ---------------- head: out[n] = LN(fx) @ head_w + head_b ----------------
__global__ void head_kernel(const float* __restrict__ fx, const float* __restrict__ g,
                            const float* __restrict__ b, const float* __restrict__ hw,
                            const float* __restrict__ hb, float* __restrict__ out) {
    __shared__ float sh[8];
    int n = blockIdx.x, t = threadIdx.x;
    float v = fx[(size_t)n * DMODEL + t];
    float mean = block_sum256(v, sh) * (1.0f / DMODEL);
    float d = v - mean;
    float var = block_sum256(d * d, sh) * (1.0f / DMODEL);
    float rstd = rsqrtf(var + 1e-5f);
    float hn = d * rstd * g[t] + b[t];
    float dot = block_sum256(hn * hw[t], sh);
    if (t == 0) out[n] = dot + hb[0];
}

// ---------------- launch ----------------
extern "C" void kernel_launch(void* const* d_in, const int* in_sizes, int n_in,
                              void* d_out, int out_size) {
    const float* x          = (const float*)d_in[0];
    const float* pre_w1     = (const float*)d_in[1];
    const float* pre_b1     = (const float*)d_in[2];
    const float* pre_w2     = (const float*)d_in[3];
    const float* pre_b2     = (const float*)d_in[4];
    const float* placeholder= (const float*)d_in[5];
    const float* ln1_g      = (const float*)d_in[6];
    const float* ln1_b      = (const float*)d_in[7];
    const float* inp_w      = (const float*)d_in[8];
    const float* inp_b      = (const float*)d_in[9];
    const float* temp_q     = (const float*)d_in[10];
    const float* temp_k     = (const float*)d_in[11];
    const float* wq         = (const float*)d_in[12];
    const float* wk         = (const float*)d_in[13];
    const float* wv         = (const float*)d_in[14];
    const float* out_w1     = (const float*)d_in[15];
    const float* out_b1     = (const float*)d_in[16];
    const float* out_w2     = (const float*)d_in[17];
    const float* out_b2     = (const float*)d_in[18];
    const float* ln2_g      = (const float*)d_in[19];
    const float* ln2_b      = (const float*)d_in[20];
    const float* mlp_w1     = (const float*)d_in[21];
    const float* mlp_b1     = (const float*)d_in[22];
    const float* mlp_w2     = (const float*)d_in[23];
    const float* mlp_b2     = (const float*)d_in[24];
    const float* ln3_g      = (const float*)d_in[25];
    const float* ln3_b      = (const float*)d_in[26];
    const float* head_w     = (const float*)d_in[27];
    const float* head_b     = (const float*)d_in[28];

    float *fx, *t1, *t2, *t3, *hidden, *kv2, *wc;
    cudaGetSymbolAddress((void**)&fx, g_fx);
    cudaGetSymbolAddress((void**)&t1, g_t1);
    cudaGetSymbolAddress((void**)&t2, g_t2);
    cudaGetSymbolAddress((void**)&t3, g_t3);
    cudaGetSymbolAddress((void**)&hidden, g_hidden);
    cudaGetSymbolAddress((void**)&kv2, g_kv2);
    cudaGetSymbolAddress((void**)&wc, g_wc);

    float* iwc   = wc;
    float* ow1c  = wc + 1 * WCONV_PER;
    float* ow2c  = wc + 2 * WCONV_PER;
    float* mw1c  = wc + 3 * WCONV_PER;
    float* mw2c  = wc + 4 * WCONV_PER;
    float* pw2c  = wc + 5 * WCONV_PER;

    const int gemm_smem = GEMM_SMEM_FLOATS * 4;
    const int kv_smem = KV_SMEM_FLOATS * 4;
    const int qkv_smem = QKV_SMEM_FLOATS * 4;
    cudaFuncSetAttribute(gemm_kernel, cudaFuncAttributeMaxDynamicSharedMemorySize, gemm_smem);
    cudaFuncSetAttribute(kv_mma_kernel, cudaFuncAttributeMaxDynamicSharedMemorySize, kv_smem);
    cudaFuncSetAttribute(qkv_mma_kernel, cudaFuncAttributeMaxDynamicSharedMemorySize, qkv_smem);

    dim3 ggrid(NPTS / TBM, DMODEL / TBN);

    // weight conversion (tf32 round once per launch)
    conv_tf32_kernel<<<(WCONV_PER / 4 + 255) / 256, 256>>>(inp_w,  iwc,  WCONV_PER / 4);
    conv_tf32_kernel<<<(WCONV_PER / 4 + 255) / 256, 256>>>(out_w1, ow1c, WCONV_PER / 4);
    conv_tf32_kernel<<<(WCONV_PER / 4 + 255) / 256, 256>>>(out_w2, ow2c, WCONV_PER / 4);
    conv_tf32_kernel<<<(WCONV_PER / 4 + 255) / 256, 256>>>(mlp_w1, mw1c, WCONV_PER / 4);
    conv_tf32_kernel<<<(WCONV_PER / 4 + 255) / 256, 256>>>(mlp_w2, mw2c, WCONV_PER / 4);
    conv_tf32_kernel<<<(131072 / 4 + 255) / 256, 256>>>(pre_w2, pw2c, 131072 / 4);

    pre1_kernel<<<NPTS * 512 / 256, 256>>>(x, pre_w1, pre_b1, hidden);
    gemm_kernel<<<ggrid, 256, gemm_smem>>>(hidden, 512, pw2c, pre_b2, placeholder, nullptr, fx, 0, 0);

    for (int i = 0; i < NLAYERS; i++) {
        const float* iw  = iwc  + (size_t)i * 65536;
        const float* ow1 = ow1c + (size_t)i * 65536;
        const float* ow2 = ow2c + (size_t)i * 65536;
        const float* mw1 = mw1c + (size_t)i * 65536;
        const float* mw2 = mw2c + (size_t)i * 65536;

        ln_kernel<<<NPTS / 8, 256>>>(fx, ln1_g + i * 256, ln1_b + i * 256, t1);
        gemm_kernel<<<ggrid, 256, gemm_smem>>>(t1, 256, iw, inp_b + i * 256, nullptr, nullptr, t2, 0, 1);
        zero_kv_kernel<<<(NH * QKDIM * 40 + 255) / 256, 256>>>();
        kv_mma_kernel<<<dim3(32, NH), 256, kv_smem>>>(t2, wk + (size_t)i * 4096,
                                                      wv + (size_t)i * 1024, temp_k + i * NH, kv2);
        qkv_mma_kernel<<<dim3(NPTS / 64, NH), 256, qkv_smem>>>(t2, wq + (size_t)i * 4096,
                                                               temp_q + i * NH, kv2, t3);
        gemm_kernel<<<ggrid, 256, gemm_smem>>>(t3, 256, ow1, out_b1 + i * 256, nullptr, nullptr, t1, 1, 1);
        gemm_kernel<<<ggrid, 256, gemm_smem>>>(t1, 256, ow2, out_b2 + i * 256, nullptr, fx, fx, 0, 0);
        ln_kernel<<<NPTS / 8, 256>>>(fx, ln2_g + i * 256, ln2_b + i * 256, t1);
        gemm_kernel<<<ggrid, 256, gemm_smem>>>(t1, 256, mw1, mlp_b1 + i * 256, nullptr, nullptr, t2, 1, 1);
        gemm_kernel<<<ggrid, 256, gemm_smem>>>(t2, 256, mw2, mlp_b2 + i * 256, nullptr, fx, fx, 0, 0);
    }
    head_kernel<<<NPTS, 256>>>(fx, ln3_g, ln3_b, head_w, head_b, (float*)d_out);
}